// round 7
// baseline (speedup 1.0000x reference)
#include <cuda_runtime.h>
#include <cuda_fp16.h>
#include <math.h>
#include <stdint.h>

#define T_  1024
#define B_  8
#define C_  1024
#define H_  16
#define D_  64
#define M_  4096
#define TA_ 1024
#define R_  (T_*B_)
#define SIXC (6*C_)

// ---------------- scratch (device globals) -----------------------------------
__device__ float  g_mod[B_*SIXC];
__device__ __half g_wh [16*1024*1024];     // packed fp16 weights
__device__ __half g_ah [(size_t)R_*C_];    // audio fp16
__device__ __half g_lnh[(size_t)R_*C_];    // ln+modulate fp16
__device__ __half g_qkv[(size_t)R_*3*C_];  // merged q|k|v fp16, row stride 3C
__device__ __half g_yh [(size_t)R_*C_];    // attention out fp16
__device__ __half g_hh [(size_t)R_*M_];    // mlp hidden fp16

#define WOFF_Q   (0)
#define WOFF_CQ  (4*1024*1024)
#define WOFF_O   (3*1024*1024)
#define WOFF_CO  (7*1024*1024)
#define WOFF_W1  (8*1024*1024)
#define WOFF_W2  (12*1024*1024)

// ---------------- helpers ----------------------------------------------------
__device__ __forceinline__ float gelu_tanh(float x) {
    float x3 = x*x*x;
    return 0.5f*x*(1.f + tanhf(0.7978845608028654f*(x + 0.044715f*x3)));
}
__device__ __forceinline__ uint32_t f2h2(float lo, float hi) {
    __half2 h = __floats2half2_rn(lo, hi);
    return *reinterpret_cast<uint32_t*>(&h);
}
__device__ __forceinline__ void mma_f16(float* d, const uint32_t* a, const uint32_t* b) {
    asm volatile(
        "mma.sync.aligned.m16n8k16.row.col.f32.f16.f16.f32 "
        "{%0,%1,%2,%3}, {%4,%5,%6,%7}, {%8,%9}, {%0,%1,%2,%3};\n"
        : "+f"(d[0]), "+f"(d[1]), "+f"(d[2]), "+f"(d[3])
        : "r"(a[0]), "r"(a[1]), "r"(a[2]), "r"(a[3]), "r"(b[0]), "r"(b[1]));
}
__device__ __forceinline__ void ldsm4(uint32_t* r, uint32_t addr) {
    asm volatile("ldmatrix.sync.aligned.m8n8.x4.shared.b16 {%0,%1,%2,%3}, [%4];"
        : "=r"(r[0]), "=r"(r[1]), "=r"(r[2]), "=r"(r[3]) : "r"(addr));
}
__device__ __forceinline__ void ldsm4t(uint32_t* r, uint32_t addr) {
    asm volatile("ldmatrix.sync.aligned.m8n8.x4.trans.shared.b16 {%0,%1,%2,%3}, [%4];"
        : "=r"(r[0]), "=r"(r[1]), "=r"(r[2]), "=r"(r[3]) : "r"(addr));
}
__device__ __forceinline__ void cpa16(uint32_t dst, const void* src) {
    asm volatile("cp.async.ca.shared.global [%0], [%1], 16;\n" :: "r"(dst), "l"(src));
}
__device__ __forceinline__ void cpa_commit() { asm volatile("cp.async.commit_group;\n"); }
__device__ __forceinline__ void cpa_wait1()  { asm volatile("cp.async.wait_group 1;\n"); }
__device__ __forceinline__ void cpa_wait0()  { asm volatile("cp.async.wait_group 0;\n"); }

// ---------------- small utility kernels --------------------------------------
__global__ void copy_k(const float* __restrict__ in, float* __restrict__ out) {
    int i = blockIdx.x*blockDim.x + threadIdx.x;
    ((float4*)out)[i] = ((const float4*)in)[i];
}
// fp32 -> fp16, 8 elems/thread, generic
__global__ void f2h_k(const float* __restrict__ in, __half* __restrict__ out) {
    int i = (blockIdx.x*256 + threadIdx.x)*8;
    float4 a = *(const float4*)&in[i];
    float4 b = *(const float4*)&in[i+4];
    *(uint4*)&out[i] = make_uint4(f2h2(a.x,a.y), f2h2(a.z,a.w),
                                  f2h2(b.x,b.y), f2h2(b.z,b.w));
}
// fused conversion of the 8 CxC weight matrices; grid (512, 8)
__global__ void f2h8_k(const float* __restrict__ p0, const float* __restrict__ p1,
                       const float* __restrict__ p2, const float* __restrict__ p3,
                       const float* __restrict__ p4, const float* __restrict__ p5,
                       const float* __restrict__ p6, const float* __restrict__ p7,
                       __half* __restrict__ out) {
    const float* src;
    switch (blockIdx.y) {
        case 0: src = p0; break; case 1: src = p1; break;
        case 2: src = p2; break; case 3: src = p3; break;
        case 4: src = p4; break; case 5: src = p5; break;
        case 6: src = p6; break; default: src = p7; break;
    }
    int i = (blockIdx.x*256 + threadIdx.x)*8;
    float4 a = *(const float4*)&src[i];
    float4 b = *(const float4*)&src[i+4];
    *(uint4*)&out[(size_t)blockIdx.y*(C_*C_) + i] =
        make_uint4(f2h2(a.x,a.y), f2h2(a.z,a.w), f2h2(b.x,b.y), f2h2(b.z,b.w));
}

// ---------------- mod = silu(c) @ w_ada + b_ada ------------------------------
__global__ void mod_k(const float* __restrict__ c, const float* __restrict__ w,
                      const float* __restrict__ bias, float* __restrict__ mod) {
    __shared__ float sc[B_][C_];
    int tid = threadIdx.x;
    for (int i = tid; i < B_*C_; i += 256) {
        float v = c[i];
        sc[i>>10][i&1023] = v / (1.f + __expf(-v));
    }
    __syncthreads();
    int col = blockIdx.x*256 + tid;
    float acc[B_];
    #pragma unroll
    for (int b = 0; b < B_; b++) acc[b] = 0.f;
    for (int k = 0; k < C_; k++) {
        float wv = w[(size_t)k*SIXC + col];
        #pragma unroll
        for (int b = 0; b < B_; b++) acc[b] += sc[b][k]*wv;
    }
    float bb = bias[col];
    #pragma unroll
    for (int b = 0; b < B_; b++) mod[b*SIXC + col] = acc[b] + bb;
}

// ---------------- LN (no affine) + modulate -> fp16 --------------------------
__global__ void ln_mod_k(const float* __restrict__ x, const float* __restrict__ mod,
                         int shiftOff, int scaleOff, __half* __restrict__ out) {
    int row = blockIdx.x;
    int b   = row & (B_-1);
    int tid = threadIdx.x;
    const float* xr = x + (size_t)row*C_;
    float4 v = *(const float4*)&xr[tid*4];
    float s  = v.x + v.y + v.z + v.w;
    float s2 = v.x*v.x + v.y*v.y + v.z*v.z + v.w*v.w;
    #pragma unroll
    for (int o = 16; o; o >>= 1) {
        s  += __shfl_xor_sync(0xffffffffu, s,  o);
        s2 += __shfl_xor_sync(0xffffffffu, s2, o);
    }
    __shared__ float red[2][8];
    int w = tid >> 5, ln = tid & 31;
    if (ln == 0) { red[0][w] = s; red[1][w] = s2; }
    __syncthreads();
    s = 0.f; s2 = 0.f;
    #pragma unroll
    for (int i = 0; i < 8; i++) { s += red[0][i]; s2 += red[1][i]; }
    float mu   = s * (1.f/C_);
    float var  = s2 * (1.f/C_) - mu*mu;
    float rstd = rsqrtf(var + 1e-6f);
    const float* sh = mod + b*SIXC + shiftOff + tid*4;
    const float* sc = mod + b*SIXC + scaleOff + tid*4;
    float4 shv = *(const float4*)sh;
    float4 scv = *(const float4*)sc;
    float m0 = (v.x-mu)*rstd*(1.f+scv.x) + shv.x;
    float m1 = (v.y-mu)*rstd*(1.f+scv.y) + shv.y;
    float m2 = (v.z-mu)*rstd*(1.f+scv.z) + shv.z;
    float m3 = (v.w-mu)*rstd*(1.f+scv.w) + shv.w;
    *(uint2*)&out[(size_t)row*C_ + tid*4] = make_uint2(f2h2(m0,m1), f2h2(m2,m3));
}

// ---------------- fp16 GEMM 128x128, BK=32, 3-stage cp.async -----------------
// As: per 16-k slice [row][8 u32], row stride SAW=12 u32 (48B)
// Bs: per 16-k slice [k][64 u32], row stride SBW=68 u32 (272B)
#define SAW 12
#define SBW 68
#define ABUF (2*128*SAW)     // u32 per stage
#define BBUF (2*16*SBW)
#define STAGES 3
#define GEMM_SMEM (STAGES*(ABUF + BBUF)*4)

template<int EPI, typename OT>
__device__ __forceinline__ void gemm_body(
    const __half* __restrict__ A, const __half* __restrict__ W,
    const float* __restrict__ bias, OT* __restrict__ out,
    const float* __restrict__ gate,
    int K, int N, int row0, int col0, size_t ostride, int ocol0)
{
    extern __shared__ __align__(16) uint32_t smg[];
    uint32_t* AsS = smg;                 // STAGES*ABUF
    uint32_t* BsS = smg + STAGES*ABUF;   // STAGES*BBUF

    int tid  = threadIdx.x;
    int lane = tid & 31, wid = tid >> 5;
    int g    = lane >> 2, tig = lane & 3;
    int wm   = wid >> 2, wn = wid & 3;       // warp tile 64m x 32n

    uint32_t sA0 = (uint32_t)__cvta_generic_to_shared(AsS);
    uint32_t sB0 = (uint32_t)__cvta_generic_to_shared(BsS);

    float acc[4][4][4];
    #pragma unroll
    for (int i = 0; i < 4; i++)
        #pragma unroll
        for (int j = 0; j < 4; j++)
            #pragma unroll
            for (int q = 0; q < 4; q++) acc[i][j][q] = 0.f;

    auto load_chunk = [&](int k0, int st) {
        #pragma unroll
        for (int p = 0; p < 2; p++) {
            int idx = tid + p*256;
            int row = idx >> 2, q = idx & 3, ks = q >> 1, hs = q & 1;
            const __half* src = A + (size_t)(row0 + row)*K + k0 + ks*16 + hs*8;
            uint32_t dst = sA0 + (st*ABUF + ks*128*SAW + row*SAW + hs*4)*4;
            cpa16(dst, src);
        }
        #pragma unroll
        for (int p = 0; p < 2; p++) {
            int idx = tid + p*256;
            int kr = idx >> 4, nc = idx & 15;
            const __half* src = W + (size_t)(k0 + kr)*N + col0 + nc*8;
            uint32_t dst = sB0 + (st*BBUF + (kr>>4)*16*SBW + (kr&15)*SBW + nc*4)*4;
            cpa16(dst, src);
        }
        cpa_commit();
    };

    int nchunk = K >> 5;
    load_chunk(0, 0);
    if (nchunk > 1) load_chunk(32, 1);

    int st = 0;
    for (int ch = 0; ch < nchunk; ch++) {
        if (ch == nchunk - 1) cpa_wait0(); else cpa_wait1();
        __syncthreads();
        if (ch + 2 < nchunk) {
            int nst = st + 2; if (nst >= STAGES) nst -= STAGES;
            load_chunk((ch + 2)*32, nst);
        }

        #pragma unroll
        for (int ks = 0; ks < 2; ks++) {
            uint32_t sA = sA0 + (st*ABUF + ks*128*SAW)*4;
            uint32_t sB = sB0 + (st*BBUF + ks*16*SBW)*4;
            uint32_t af[4][4];
            #pragma unroll
            for (int mt = 0; mt < 4; mt++) {
                uint32_t addr = sA + ((wm*64 + mt*16 + (lane & 15))*SAW + ((lane >> 4) << 2))*4;
                ldsm4(af[mt], addr);
            }
            uint32_t bq[2][4];
            #pragma unroll
            for (int hf = 0; hf < 2; hf++) {
                uint32_t addr = sB + ((lane & 15)*SBW + (wn*16 + hf*8) + ((lane >> 4) << 2))*4;
                ldsm4t(bq[hf], addr);
            }
            #pragma unroll
            for (int mt = 0; mt < 4; mt++)
                #pragma unroll
                for (int nt = 0; nt < 4; nt++)
                    mma_f16(acc[mt][nt], af[mt], &bq[nt >> 1][(nt & 1)*2]);
        }
        if (++st >= STAGES) st = 0;
    }

    #pragma unroll
    for (int mt = 0; mt < 4; mt++) {
        int rbase = row0 + wm*64 + mt*16 + g;
        #pragma unroll
        for (int half = 0; half < 2; half++) {
            int rr = rbase + 8*half;
            int bb = rr & (B_-1);
            OT* orow = out + (size_t)rr*ostride + ocol0;
            #pragma unroll
            for (int nt = 0; nt < 4; nt++) {
                int cl = col0 + wn*32 + nt*8 + 2*tig;
                float v0 = acc[mt][nt][2*half + 0] + bias[cl];
                float v1 = acc[mt][nt][2*half + 1] + bias[cl+1];
                if (EPI == 2) {
                    float* fr = (float*)orow;
                    fr[cl]   += gate[bb*SIXC + cl  ]*v0;
                    fr[cl+1] += gate[bb*SIXC + cl+1]*v1;
                } else if (EPI == 1) {
                    *(uint32_t*)&orow[cl] = f2h2(gelu_tanh(v0), gelu_tanh(v1));
                } else {
                    *(uint32_t*)&orow[cl] = f2h2(v0, v1);
                }
            }
        }
    }
}

template<int EPI, typename OT>
__global__ void __launch_bounds__(256, 2)
hgemm_k(const __half* __restrict__ A, const __half* __restrict__ W,
        const float* __restrict__ bias, OT* __restrict__ out,
        const float* __restrict__ gate, int K, int N) {
    gemm_body<EPI, OT>(A, W, bias, out, gate, K, N,
                       blockIdx.y*128, blockIdx.x*128, N, 0);
}

// merged q/k/v projection: grid.x = 24 (3 mats x 8 col-blocks); out stride 3C
__global__ void __launch_bounds__(256, 2)
hgemm_qkv_k(const __half* __restrict__ A0, const __half* __restrict__ A12,
            const __half* __restrict__ Wbase,
            const float* __restrict__ b0, const float* __restrict__ b1,
            const float* __restrict__ b2,
            __half* __restrict__ out, int woff0, int K) {
    int sel = blockIdx.x >> 3;
    int nb  = blockIdx.x & 7;
    const __half* A    = (sel == 0) ? A0 : A12;
    const __half* W    = Wbase + woff0 + sel*(C_*C_);
    const float* bias  = (sel == 0) ? b0 : (sel == 1) ? b1 : b2;
    gemm_body<0, __half>(A, W, bias, out, nullptr, K, C_,
                         blockIdx.y*128, nb*128, 3*C_, sel*C_);
}

// ---------------- fp16 tensor-core flash attention ---------------------------
#define AQW 36
#define SSW 68
__global__ void __launch_bounds__(256, 2)
fattn_k(const __half* __restrict__ QKV, const int* __restrict__ mask,
        __half* __restrict__ Y, int Tk) {
    extern __shared__ uint32_t smu[];
    uint32_t* Qs = smu;
    uint32_t* Ks = Qs + 64*AQW;
    uint32_t* Vs = Ks + 64*AQW;
    uint32_t* Ps = Vs + 64*AQW;
    float*    Ssf  = (float*)(Ps + 64*AQW);
    float*    mrow = Ssf + 64*SSW;
    float*    lrow = mrow + 64;
    float*    srow = lrow + 64;
    int*      Ms   = (int*)(srow + 64);

    int tid  = threadIdx.x;
    int lane = tid & 31, wid = tid >> 5;
    int g    = lane >> 2, tig = lane & 3;
    int wm   = wid >> 1, wn = wid & 1;
    int q0 = blockIdx.x*64, h = blockIdx.y, b = blockIdx.z;
    size_t hoff = (size_t)h*D_;
    const int RS = 3*C_;
    const __half* Kp = QKV + C_;
    const __half* Vp = QKV + 2*C_;

    uint32_t vbase = (uint32_t)__cvta_generic_to_shared(Vs);

    #pragma unroll
    for (int p = 0; p < 2; p++) {
        int idx = tid + p*256;
        int r = idx >> 3, c8 = idx & 7;
        uint4 v = *(const uint4*)&QKV[((size_t)(q0+r)*B_ + b)*RS + hoff + c8*8];
        *(uint4*)&Qs[r*AQW + c8*4] = v;
    }
    if (tid < 64) { mrow[tid] = -1e30f; lrow[tid] = 0.f; }

    float oacc[4][4];
    #pragma unroll
    for (int i = 0; i < 4; i++)
        #pragma unroll
        for (int j = 0; j < 4; j++) oacc[i][j] = 0.f;
    __syncthreads();

    for (int k0 = 0; k0 < Tk; k0 += 64) {
        #pragma unroll
        for (int p = 0; p < 2; p++) {
            int idx = tid + p*256;
            int r = idx >> 3, c8 = idx & 7;
            size_t gi = ((size_t)(k0+r)*B_ + b)*RS + hoff + c8*8;
            *(uint4*)&Ks[r*AQW + c8*4] = *(const uint4*)&Kp[gi];
            *(uint4*)&Vs[r*AQW + c8*4] = *(const uint4*)&Vp[gi];
        }
        if (tid < 64) Ms[tid] = mask[(size_t)b*Tk + k0 + tid];
        __syncthreads();

        float sacc[4][4];
        #pragma unroll
        for (int i = 0; i < 4; i++)
            #pragma unroll
            for (int j = 0; j < 4; j++) sacc[i][j] = 0.f;
        #pragma unroll
        for (int ks = 0; ks < 4; ks++) {
            uint32_t af[4];
            const uint32_t* qp = &Qs[(wm*16 + g)*AQW + ks*8 + tig];
            af[0] = qp[0]; af[1] = qp[8*AQW]; af[2] = qp[4]; af[3] = qp[8*AQW + 4];
            #pragma unroll
            for (int nt = 0; nt < 4; nt++) {
                int nr = wn*32 + nt*8 + g;
                uint32_t bf[2];
                bf[0] = Ks[nr*AQW + ks*8 + tig];
                bf[1] = Ks[nr*AQW + ks*8 + tig + 4];
                mma_f16(sacc[nt], af, bf);
            }
        }
        #pragma unroll
        for (int nt = 0; nt < 4; nt++) {
            int cc = wn*32 + nt*8 + 2*tig;
            int r0 = wm*16 + g;
            *(float2*)&Ssf[ r0     *SSW + cc] = make_float2(sacc[nt][0], sacc[nt][1]);
            *(float2*)&Ssf[(r0 + 8)*SSW + cc] = make_float2(sacc[nt][2], sacc[nt][3]);
        }
        __syncthreads();

        {
            int r  = tid >> 2, c0 = (tid & 3)*16;
            float s[16];
            #pragma unroll
            for (int j = 0; j < 16; j++)
                s[j] = Ms[c0 + j] ? -1e30f : Ssf[r*SSW + c0 + j]*0.125f;
            float mx = s[0];
            #pragma unroll
            for (int j = 1; j < 16; j++) mx = fmaxf(mx, s[j]);
            mx = fmaxf(mx, __shfl_xor_sync(0xffffffffu, mx, 1));
            mx = fmaxf(mx, __shfl_xor_sync(0xffffffffu, mx, 2));
            float mold = mrow[r];
            float mnew = fmaxf(mold, mx);
            float p[16];
            float rs = 0.f;
            #pragma unroll
            for (int j = 0; j < 16; j++) {
                p[j] = (s[j] > -1e29f) ? __expf(s[j] - mnew) : 0.f;
                rs += p[j];
            }
            uint32_t* pr = &Ps[r*AQW + (c0>>1)];
            #pragma unroll
            for (int j = 0; j < 8; j++) pr[j] = f2h2(p[2*j], p[2*j+1]);
            rs += __shfl_xor_sync(0xffffffffu, rs, 1);
            rs += __shfl_xor_sync(0xffffffffu, rs, 2);
            if ((tid & 3) == 0) {
                float scl = __expf(mold - mnew);
                lrow[r] = lrow[r]*scl + rs;
                mrow[r] = mnew;
                srow[r] = scl;
            }
        }
        __syncthreads();

        float s0 = srow[wm*16 + g];
        float s1 = srow[wm*16 + g + 8];
        #pragma unroll
        for (int nt = 0; nt < 4; nt++) {
            oacc[nt][0] *= s0; oacc[nt][1] *= s0;
            oacc[nt][2] *= s1; oacc[nt][3] *= s1;
        }
        #pragma unroll
        for (int ks = 0; ks < 4; ks++) {
            uint32_t af[4];
            const uint32_t* pp = &Ps[(wm*16 + g)*AQW + ks*8 + tig];
            af[0] = pp[0]; af[1] = pp[8*AQW]; af[2] = pp[4]; af[3] = pp[8*AQW + 4];
            uint32_t bq[2][4];
            #pragma unroll
            for (int hf = 0; hf < 2; hf++) {
                uint32_t addr = vbase +
                    ((ks*16 + (lane & 15))*AQW + (wn*16 + hf*8) + ((lane >> 4) << 2))*4;
                ldsm4t(bq[hf], addr);
            }
            #pragma unroll
            for (int nt = 0; nt < 4; nt++)
                mma_f16(oacc[nt], af, &bq[nt >> 1][(nt & 1)*2]);
        }
        __syncthreads();
    }

    float inv0 = 1.f / lrow[wm*16 + g];
    float inv1 = 1.f / lrow[wm*16 + g + 8];
    int r0 = q0 + wm*16 + g;
    #pragma unroll
    for (int nt = 0; nt < 4; nt++) {
        int dd = wn*32 + nt*8 + 2*tig;
        *(uint32_t*)&Y[((size_t) r0     *B_ + b)*C_ + hoff + dd] =
            f2h2(oacc[nt][0]*inv0, oacc[nt][1]*inv0);
        *(uint32_t*)&Y[((size_t)(r0 + 8)*B_ + b)*C_ + hoff + dd] =
            f2h2(oacc[nt][2]*inv1, oacc[nt][3]*inv1);
    }
}

// ---------------- launch -----------------------------------------------------
extern "C" void kernel_launch(void* const* d_in, const int* in_sizes, int n_in,
                              void* d_out, int out_size) {
    const float* x     = (const float*)d_in[0];
    const float* c     = (const float*)d_in[1];
    const int*   pmask = (const int*)  d_in[2];
    const float* audio = (const float*)d_in[3];
    const int*   amask = (const int*)  d_in[4];
    const float* w_ada = (const float*)d_in[5];
    const float* b_ada = (const float*)d_in[6];
    const float* wq = (const float*)d_in[7];   const float* bq = (const float*)d_in[8];
    const float* wk = (const float*)d_in[9];   const float* bk = (const float*)d_in[10];
    const float* wv = (const float*)d_in[11];  const float* bv = (const float*)d_in[12];
    const float* wo = (const float*)d_in[13];  const float* bo = (const float*)d_in[14];
    const float* cwq = (const float*)d_in[15]; const float* cbq = (const float*)d_in[16];
    const float* cwk = (const float*)d_in[17]; const float* cbk = (const float*)d_in[18];
    const float* cwv = (const float*)d_in[19]; const float* cbv = (const float*)d_in[20];
    const float* cwo = (const float*)d_in[21]; const float* cbo = (const float*)d_in[22];
    const float* w1 = (const float*)d_in[23];  const float* b1 = (const float*)d_in[24];
    const float* w2 = (const float*)d_in[25];  const float* b2 = (const float*)d_in[26];
    float* out = (float*)d_out;

    float  *modp;
    __half *whp, *ahp, *lnp, *qkvp, *yp, *hp;
    cudaGetSymbolAddress((void**)&modp, g_mod);
    cudaGetSymbolAddress((void**)&whp,  g_wh);
    cudaGetSymbolAddress((void**)&ahp,  g_ah);
    cudaGetSymbolAddress((void**)&lnp,  g_lnh);
    cudaGetSymbolAddress((void**)&qkvp, g_qkv);
    cudaGetSymbolAddress((void**)&yp,   g_yh);
    cudaGetSymbolAddress((void**)&hp,   g_hh);

    int attn_smem = (4*64*AQW + 64*SSW + 3*64 + 64)*sizeof(uint32_t);
    cudaFuncSetAttribute(fattn_k, cudaFuncAttributeMaxDynamicSharedMemorySize, attn_smem);
    cudaFuncSetAttribute((const void*)hgemm_k<2, float>,
                         cudaFuncAttributeMaxDynamicSharedMemorySize, GEMM_SMEM);
    cudaFuncSetAttribute((const void*)hgemm_k<1, __half>,
                         cudaFuncAttributeMaxDynamicSharedMemorySize, GEMM_SMEM);
    cudaFuncSetAttribute((const void*)hgemm_qkv_k,
                         cudaFuncAttributeMaxDynamicSharedMemorySize, GEMM_SMEM);

    dim3 gQKV(24, 64);
    dim3 gC(8, 64);
    dim3 gM(32, 64);
    dim3 gA(T_/64, H_, B_);

    copy_k<<<(R_*C_)/1024, 256>>>(x, out);
    mod_k<<<SIXC/256, 256>>>(c, w_ada, b_ada, modp);
    // fused weight conversion: order q,k,v,o,cq,ck,cv,co matches offsets 0..7M
    f2h8_k<<<dim3((C_*C_)/2048, 8), 256>>>(wq, wk, wv, wo, cwq, cwk, cwv, cwo, whp);
    f2h_k<<<(C_*M_)/2048, 256>>>(w1, whp + WOFF_W1);
    f2h_k<<<(M_*C_)/2048, 256>>>(w2, whp + WOFF_W2);
    f2h_k<<<(R_*C_)/2048, 256>>>(audio, ahp);

    // ---- self attention ----
    ln_mod_k<<<R_, 256>>>(out, modp, 0, C_, lnp);
    hgemm_qkv_k<<<gQKV, 256, GEMM_SMEM>>>(lnp, lnp, whp, bq, bk, bv, qkvp, WOFF_Q, C_);
    fattn_k<<<gA, 256, attn_smem>>>(qkvp, pmask, yp, T_);
    hgemm_k<2, float><<<gC, 256, GEMM_SMEM>>>(yp, whp + WOFF_O, bo, out, modp + 2*C_, C_, C_);

    // ---- cross attention (reuses msa shift/scale/gate) ----
    ln_mod_k<<<R_, 256>>>(out, modp, 0, C_, lnp);
    hgemm_qkv_k<<<gQKV, 256, GEMM_SMEM>>>(lnp, ahp, whp, cbq, cbk, cbv, qkvp, WOFF_CQ, C_);
    fattn_k<<<gA, 256, attn_smem>>>(qkvp, amask, yp, TA_);
    hgemm_k<2, float><<<gC, 256, GEMM_SMEM>>>(yp, whp + WOFF_CO, cbo, out, modp + 2*C_, C_, C_);

    // ---- MLP ----
    ln_mod_k<<<R_, 256>>>(out, modp, 3*C_, 4*C_, lnp);
    hgemm_k<1, __half><<<gM, 256, GEMM_SMEM>>>(lnp, whp + WOFF_W1, b1, hp, nullptr, C_, M_);
    hgemm_k<2, float><<<gC, 256, GEMM_SMEM>>>(hp, whp + WOFF_W2, b2, out, modp + 5*C_, M_, C_);
}

// round 10
// speedup vs baseline: 1.2285x; 1.2285x over previous
#include <cuda_runtime.h>
#include <cuda_fp16.h>
#include <math.h>
#include <stdint.h>

#define T_  1024
#define B_  8
#define C_  1024
#define H_  16
#define D_  64
#define M_  4096
#define TA_ 1024
#define R_  (T_*B_)
#define SIXC (6*C_)

// ---------------- scratch (device globals) -----------------------------------
__device__ float  g_mod[B_*SIXC];
__device__ __half g_wh [16*1024*1024];     // packed fp16 weights [K,N]
__device__ __half g_ah [(size_t)R_*C_];    // audio fp16
__device__ __half g_lnh[(size_t)R_*C_];    // ln+modulate fp16
__device__ __half g_qkv[(size_t)R_*3*C_];  // merged q|k|v fp16, row stride 3C
__device__ __half g_yh [(size_t)R_*C_];    // attention out fp16
__device__ __half g_hh [(size_t)R_*M_];    // mlp hidden fp16

#define WOFF_Q   (0)
#define WOFF_O   (3*1024*1024)
#define WOFF_CQ  (4*1024*1024)
#define WOFF_CO  (7*1024*1024)
#define WOFF_W1  (8*1024*1024)
#define WOFF_W2  (12*1024*1024)

// ---------------- helpers ----------------------------------------------------
__device__ __forceinline__ float gelu_tanh(float x) {
    float x3 = x*x*x;
    return 0.5f*x*(1.f + tanhf(0.7978845608028654f*(x + 0.044715f*x3)));
}
__device__ __forceinline__ uint32_t f2h2(float lo, float hi) {
    __half2 h = __floats2half2_rn(lo, hi);
    return *reinterpret_cast<uint32_t*>(&h);
}
__device__ __forceinline__ void mma_f16(float* d, const uint32_t* a, const uint32_t* b) {
    asm volatile(
        "mma.sync.aligned.m16n8k16.row.col.f32.f16.f16.f32 "
        "{%0,%1,%2,%3}, {%4,%5,%6,%7}, {%8,%9}, {%0,%1,%2,%3};\n"
        : "+f"(d[0]), "+f"(d[1]), "+f"(d[2]), "+f"(d[3])
        : "r"(a[0]), "r"(a[1]), "r"(a[2]), "r"(a[3]), "r"(b[0]), "r"(b[1]));
}
__device__ __forceinline__ void ldsm4(uint32_t* r, uint32_t addr) {
    asm volatile("ldmatrix.sync.aligned.m8n8.x4.shared.b16 {%0,%1,%2,%3}, [%4];"
        : "=r"(r[0]), "=r"(r[1]), "=r"(r[2]), "=r"(r[3]) : "r"(addr));
}
__device__ __forceinline__ void ldsm4t(uint32_t* r, uint32_t addr) {
    asm volatile("ldmatrix.sync.aligned.m8n8.x4.trans.shared.b16 {%0,%1,%2,%3}, [%4];"
        : "=r"(r[0]), "=r"(r[1]), "=r"(r[2]), "=r"(r[3]) : "r"(addr));
}
__device__ __forceinline__ void cpa16(uint32_t dst, const void* src) {
    asm volatile("cp.async.ca.shared.global [%0], [%1], 16;\n" :: "r"(dst), "l"(src));
}
__device__ __forceinline__ void cpa_commit() { asm volatile("cp.async.commit_group;\n"); }
__device__ __forceinline__ void cpa_wait1()  { asm volatile("cp.async.wait_group 1;\n"); }
__device__ __forceinline__ void cpa_wait0()  { asm volatile("cp.async.wait_group 0;\n"); }

// ---------------- small utility kernels --------------------------------------
__global__ void copy_k(const float* __restrict__ in, float* __restrict__ out) {
    int i = blockIdx.x*blockDim.x + threadIdx.x;
    ((float4*)out)[i] = ((const float4*)in)[i];
}
__global__ void f2h_k(const float* __restrict__ in, __half* __restrict__ out) {
    int i = (blockIdx.x*256 + threadIdx.x)*8;
    float4 a = *(const float4*)&in[i];
    float4 b = *(const float4*)&in[i+4];
    *(uint4*)&out[i] = make_uint4(f2h2(a.x,a.y), f2h2(a.z,a.w),
                                  f2h2(b.x,b.y), f2h2(b.z,b.w));
}
// fused conversion of the 8 CxC weight matrices; grid (512, 8)
__global__ void f2h8_k(const float* __restrict__ p0, const float* __restrict__ p1,
                       const float* __restrict__ p2, const float* __restrict__ p3,
                       const float* __restrict__ p4, const float* __restrict__ p5,
                       const float* __restrict__ p6, const float* __restrict__ p7,
                       __half* __restrict__ out) {
    const float* src;
    switch (blockIdx.y) {
        case 0: src = p0; break; case 1: src = p1; break;
        case 2: src = p2; break; case 3: src = p3; break;
        case 4: src = p4; break; case 5: src = p5; break;
        case 6: src = p6; break; default: src = p7; break;
    }
    int i = (blockIdx.x*256 + threadIdx.x)*8;
    float4 a = *(const float4*)&src[i];
    float4 b = *(const float4*)&src[i+4];
    *(uint4*)&out[(size_t)blockIdx.y*(C_*C_) + i] =
        make_uint4(f2h2(a.x,a.y), f2h2(a.z,a.w), f2h2(b.x,b.y), f2h2(b.z,b.w));
}

// ---------------- mod = silu(c) @ w_ada + b_ada ------------------------------
__global__ void mod_k(const float* __restrict__ c, const float* __restrict__ w,
                      const float* __restrict__ bias, float* __restrict__ mod) {
    __shared__ float sc[B_][C_];
    int tid = threadIdx.x;
    for (int i = tid; i < B_*C_; i += 256) {
        float v = c[i];
        sc[i>>10][i&1023] = v / (1.f + __expf(-v));
    }
    __syncthreads();
    int col = blockIdx.x*256 + tid;
    float acc[B_];
    #pragma unroll
    for (int b = 0; b < B_; b++) acc[b] = 0.f;
    for (int k = 0; k < C_; k++) {
        float wv = w[(size_t)k*SIXC + col];
        #pragma unroll
        for (int b = 0; b < B_; b++) acc[b] += sc[b][k]*wv;
    }
    float bb = bias[col];
    #pragma unroll
    for (int b = 0; b < B_; b++) mod[b*SIXC + col] = acc[b] + bb;
}

// ---------------- LN (no affine) + modulate -> fp16 --------------------------
__global__ void ln_mod_k(const float* __restrict__ x, const float* __restrict__ mod,
                         int shiftOff, int scaleOff, __half* __restrict__ out) {
    int row = blockIdx.x;
    int b   = row & (B_-1);
    int tid = threadIdx.x;
    const float* xr = x + (size_t)row*C_;
    float4 v = *(const float4*)&xr[tid*4];
    float s  = v.x + v.y + v.z + v.w;
    float s2 = v.x*v.x + v.y*v.y + v.z*v.z + v.w*v.w;
    #pragma unroll
    for (int o = 16; o; o >>= 1) {
        s  += __shfl_xor_sync(0xffffffffu, s,  o);
        s2 += __shfl_xor_sync(0xffffffffu, s2, o);
    }
    __shared__ float red[2][8];
    int w = tid >> 5, ln = tid & 31;
    if (ln == 0) { red[0][w] = s; red[1][w] = s2; }
    __syncthreads();
    s = 0.f; s2 = 0.f;
    #pragma unroll
    for (int i = 0; i < 8; i++) { s += red[0][i]; s2 += red[1][i]; }
    float mu   = s * (1.f/C_);
    float var  = s2 * (1.f/C_) - mu*mu;
    float rstd = rsqrtf(var + 1e-6f);
    const float* sh = mod + b*SIXC + shiftOff + tid*4;
    const float* sc = mod + b*SIXC + scaleOff + tid*4;
    float4 shv = *(const float4*)sh;
    float4 scv = *(const float4*)sc;
    float m0 = (v.x-mu)*rstd*(1.f+scv.x) + shv.x;
    float m1 = (v.y-mu)*rstd*(1.f+scv.y) + shv.y;
    float m2 = (v.z-mu)*rstd*(1.f+scv.z) + shv.z;
    float m3 = (v.w-mu)*rstd*(1.f+scv.w) + shv.w;
    *(uint2*)&out[(size_t)row*C_ + tid*4] = make_uint2(f2h2(m0,m1), f2h2(m2,m3));
}

// ---------------- fp16 GEMM 128x128, BK=32, cp.async double buffer (round-6) -
#define SAW 12
#define SBW 68
#define ABUF (2*128*SAW)
#define BBUF (2*16*SBW)

template<int EPI, typename OT>
__device__ __forceinline__ void gemm_body(
    uint32_t* AsS, uint32_t* BsS,
    const __half* __restrict__ A, const __half* __restrict__ W,
    const float* __restrict__ bias, OT* __restrict__ out,
    const float* __restrict__ gate,
    int K, int N, int row0, int col0, size_t ostride, int ocol0)
{
    int tid  = threadIdx.x;
    int lane = tid & 31, wid = tid >> 5;
    int g    = lane >> 2, tig = lane & 3;
    int wm   = wid >> 2, wn = wid & 3;

    uint32_t sA0 = (uint32_t)__cvta_generic_to_shared(AsS);
    uint32_t sB0 = (uint32_t)__cvta_generic_to_shared(BsS);

    float acc[4][4][4];
    #pragma unroll
    for (int i = 0; i < 4; i++)
        #pragma unroll
        for (int j = 0; j < 4; j++)
            #pragma unroll
            for (int q = 0; q < 4; q++) acc[i][j][q] = 0.f;

    auto load_chunk = [&](int k0, int bf) {
        #pragma unroll
        for (int p = 0; p < 2; p++) {
            int idx = tid + p*256;
            int row = idx >> 2, q = idx & 3, ks = q >> 1, hs = q & 1;
            const __half* src = A + (size_t)(row0 + row)*K + k0 + ks*16 + hs*8;
            uint32_t dst = sA0 + (bf*ABUF + ks*128*SAW + row*SAW + hs*4)*4;
            cpa16(dst, src);
        }
        #pragma unroll
        for (int p = 0; p < 2; p++) {
            int idx = tid + p*256;
            int kr = idx >> 4, nc = idx & 15;
            const __half* src = W + (size_t)(k0 + kr)*N + col0 + nc*8;
            uint32_t dst = sB0 + (bf*BBUF + (kr>>4)*16*SBW + (kr&15)*SBW + nc*4)*4;
            cpa16(dst, src);
        }
        cpa_commit();
    };

    load_chunk(0, 0);

    int buf = 0;
    int nchunk = K >> 5;
    for (int ch = 0; ch < nchunk; ch++) {
        bool more = (ch + 1 < nchunk);
        if (more) { load_chunk((ch + 1)*32, buf ^ 1); cpa_wait1(); }
        else      { cpa_wait0(); }
        __syncthreads();

        #pragma unroll
        for (int ks = 0; ks < 2; ks++) {
            uint32_t sA = sA0 + (buf*ABUF + ks*128*SAW)*4;
            uint32_t sB = sB0 + (buf*BBUF + ks*16*SBW)*4;
            uint32_t af[4][4];
            #pragma unroll
            for (int mt = 0; mt < 4; mt++) {
                uint32_t addr = sA + ((wm*64 + mt*16 + (lane & 15))*SAW + ((lane >> 4) << 2))*4;
                ldsm4(af[mt], addr);
            }
            uint32_t bq[2][4];
            #pragma unroll
            for (int hf = 0; hf < 2; hf++) {
                uint32_t addr = sB + ((lane & 15)*SBW + (wn*16 + hf*8) + ((lane >> 4) << 2))*4;
                ldsm4t(bq[hf], addr);
            }
            #pragma unroll
            for (int mt = 0; mt < 4; mt++)
                #pragma unroll
                for (int nt = 0; nt < 4; nt++)
                    mma_f16(acc[mt][nt], af[mt], &bq[nt >> 1][(nt & 1)*2]);
        }
        __syncthreads();
        buf ^= 1;
    }

    #pragma unroll
    for (int mt = 0; mt < 4; mt++) {
        int rbase = row0 + wm*64 + mt*16 + g;
        #pragma unroll
        for (int half = 0; half < 2; half++) {
            int rr = rbase + 8*half;
            int bb = rr & (B_-1);
            OT* orow = out + (size_t)rr*ostride + ocol0;
            #pragma unroll
            for (int nt = 0; nt < 4; nt++) {
                int cl = col0 + wn*32 + nt*8 + 2*tig;
                float v0 = acc[mt][nt][2*half + 0] + bias[cl];
                float v1 = acc[mt][nt][2*half + 1] + bias[cl+1];
                if (EPI == 2) {
                    float* fr = (float*)orow;
                    fr[cl]   += gate[bb*SIXC + cl  ]*v0;
                    fr[cl+1] += gate[bb*SIXC + cl+1]*v1;
                } else if (EPI == 1) {
                    *(uint32_t*)&orow[cl] = f2h2(gelu_tanh(v0), gelu_tanh(v1));
                } else {
                    *(uint32_t*)&orow[cl] = f2h2(v0, v1);
                }
            }
        }
    }
}

template<int EPI, typename OT>
__global__ void __launch_bounds__(256, 2)
hgemm_k(const __half* __restrict__ A, const __half* __restrict__ W,
        const float* __restrict__ bias, OT* __restrict__ out,
        const float* __restrict__ gate, int K, int N) {
    __shared__ __align__(16) uint32_t As[2*ABUF];
    __shared__ __align__(16) uint32_t Bs[2*BBUF];
    gemm_body<EPI, OT>(As, Bs, A, W, bias, out, gate, K, N,
                       blockIdx.y*128, blockIdx.x*128, N, 0);
}

__global__ void __launch_bounds__(256, 2)
hgemm_qkv_k(const __half* __restrict__ A0, const __half* __restrict__ A12,
            const __half* __restrict__ Wbase,
            const float* __restrict__ b0, const float* __restrict__ b1,
            const float* __restrict__ b2,
            __half* __restrict__ out, int woff0, int K) {
    __shared__ __align__(16) uint32_t As[2*ABUF];
    __shared__ __align__(16) uint32_t Bs[2*BBUF];
    int sel = blockIdx.x >> 3;
    int nb  = blockIdx.x & 7;
    const __half* A    = (sel == 0) ? A0 : A12;
    const __half* W    = Wbase + woff0 + sel*(C_*C_);
    const float* bias  = (sel == 0) ? b0 : (sel == 1) ? b1 : b2;
    gemm_body<0, __half>(As, Bs, A, W, bias, out, nullptr, K, C_,
                         blockIdx.y*128, nb*128, 3*C_, sel*C_);
}

// ---------------- register-resident fp16 flash attention ---------------------
// Q tile 128, K tile 64. 8 warps; warp wid owns q-rows wid*16..+15 and ALL 64 keys.
// S/softmax/P stay in registers (C-frag -> A-frag repack). K/V double-buffered cp.async.
#define KVW 36
#define ATT_SMEM ((128*KVW + 4*64*KVW)*4 + 1024*4)
__global__ void __launch_bounds__(256, 2)
fattn_k(const __half* __restrict__ QKV, const int* __restrict__ mask,
        __half* __restrict__ Y, int Tk) {
    extern __shared__ uint32_t smu[];
    uint32_t* Qs = smu;                    // 128 x KVW
    uint32_t* Ks = Qs + 128*KVW;           // 2 x 64 x KVW
    uint32_t* Vs = Ks + 2*64*KVW;          // 2 x 64 x KVW
    int*      Msk = (int*)(Vs + 2*64*KVW); // Tk ints (<=1024)

    int tid  = threadIdx.x;
    int lane = tid & 31, wid = tid >> 5;
    int g    = lane >> 2, tig = lane & 3;
    int qbase = wid*16;
    int q0 = blockIdx.x*128, h = blockIdx.y, b = blockIdx.z;
    size_t hoff = (size_t)h*D_;
    const int RS = 3*C_;
    const __half* Kp = QKV + C_;
    const __half* Vp = QKV + 2*C_;

    uint32_t sQ = (uint32_t)__cvta_generic_to_shared(Qs);
    uint32_t sK = (uint32_t)__cvta_generic_to_shared(Ks);
    uint32_t sV = (uint32_t)__cvta_generic_to_shared(Vs);

    // mask row -> smem (Tk=1024: one int4 per thread)
    for (int i = tid; i < (Tk >> 2); i += 256)
        *(int4*)&Msk[i*4] = *(const int4*)&mask[(size_t)b*Tk + i*4];

    // Q tile 128x64 -> smem
    #pragma unroll
    for (int p = 0; p < 4; p++) {
        int idx = tid + p*256;
        int r = idx >> 3, c8 = idx & 7;
        *(uint4*)&Qs[r*KVW + c8*4] =
            *(const uint4*)&QKV[((size_t)(q0+r)*B_ + b)*RS + hoff + c8*8];
    }

    auto load_kv = [&](int k0, int bf) {
        #pragma unroll
        for (int p = 0; p < 2; p++) {
            int idx = tid + p*256;
            int r = idx >> 3, c8 = idx & 7;
            size_t gi = ((size_t)(k0+r)*B_ + b)*RS + hoff + c8*8;
            uint32_t off = (bf*64*KVW + r*KVW + c8*4)*4;
            cpa16(sK + off, Kp + gi);
            cpa16(sV + off, Vp + gi);
        }
        cpa_commit();
    };
    load_kv(0, 0);

    float m0 = -1e30f, m1 = -1e30f, l0 = 0.f, l1 = 0.f;
    float oacc[8][4];
    #pragma unroll
    for (int i = 0; i < 8; i++)
        #pragma unroll
        for (int j = 0; j < 4; j++) oacc[i][j] = 0.f;

    uint32_t qaddr = sQ + ((qbase + (lane & 15))*KVW + ((lane >> 4) << 2))*4;
    uint32_t vfix  = ((lane & 15)*KVW + ((lane >> 4) << 2))*4;

    int ntile = Tk >> 6;
    for (int kt = 0; kt < ntile; kt++) {
        int buf = kt & 1;
        cpa_wait0();
        __syncthreads();                       // buf ready; buf^1 free for reload
        if (kt + 1 < ntile) load_kv((kt + 1)*64, buf ^ 1);

        const uint32_t* Ksb = Ks + buf*64*KVW;
        // ---- S = Q K^T in registers ----
        float sacc[8][4];
        #pragma unroll
        for (int i = 0; i < 8; i++)
            #pragma unroll
            for (int j = 0; j < 4; j++) sacc[i][j] = 0.f;
        #pragma unroll
        for (int ks = 0; ks < 4; ks++) {
            uint32_t qf[4];
            ldsm4(qf, qaddr + ks*32);
            #pragma unroll
            for (int nt = 0; nt < 8; nt++) {
                uint32_t bf[2];
                const uint32_t* kp = &Ksb[(nt*8 + g)*KVW + ks*8 + tig];
                bf[0] = kp[0]; bf[1] = kp[4];
                mma_f16(sacc[nt], qf, bf);
            }
        }

        // ---- softmax (registers + shfl over tig bits) ----
        float mx0 = -1e30f, mx1 = -1e30f;
        #pragma unroll
        for (int nt = 0; nt < 8; nt++) {
            int2 mm = *(const int2*)&Msk[kt*64 + nt*8 + 2*tig];
            sacc[nt][0] = mm.x ? -1e30f : sacc[nt][0]*0.125f;
            sacc[nt][1] = mm.y ? -1e30f : sacc[nt][1]*0.125f;
            sacc[nt][2] = mm.x ? -1e30f : sacc[nt][2]*0.125f;
            sacc[nt][3] = mm.y ? -1e30f : sacc[nt][3]*0.125f;
            mx0 = fmaxf(mx0, fmaxf(sacc[nt][0], sacc[nt][1]));
            mx1 = fmaxf(mx1, fmaxf(sacc[nt][2], sacc[nt][3]));
        }
        mx0 = fmaxf(mx0, __shfl_xor_sync(0xffffffffu, mx0, 1));
        mx0 = fmaxf(mx0, __shfl_xor_sync(0xffffffffu, mx0, 2));
        mx1 = fmaxf(mx1, __shfl_xor_sync(0xffffffffu, mx1, 1));
        mx1 = fmaxf(mx1, __shfl_xor_sync(0xffffffffu, mx1, 2));
        float mn0 = fmaxf(m0, mx0), mn1 = fmaxf(m1, mx1);
        float scl0 = __expf(m0 - mn0), scl1 = __expf(m1 - mn1);
        m0 = mn0; m1 = mn1;

        uint32_t pf[4][4];
        float rs0 = 0.f, rs1 = 0.f;
        #pragma unroll
        for (int nt = 0; nt < 8; nt++) {
            float p0 = (sacc[nt][0] > -1e29f) ? __expf(sacc[nt][0] - mn0) : 0.f;
            float p1 = (sacc[nt][1] > -1e29f) ? __expf(sacc[nt][1] - mn0) : 0.f;
            float p2 = (sacc[nt][2] > -1e29f) ? __expf(sacc[nt][2] - mn1) : 0.f;
            float p3 = (sacc[nt][3] > -1e29f) ? __expf(sacc[nt][3] - mn1) : 0.f;
            rs0 += p0 + p1; rs1 += p2 + p3;
            pf[nt >> 1][0 + 2*(nt & 1)] = f2h2(p0, p1);   // row g
            pf[nt >> 1][1 + 2*(nt & 1)] = f2h2(p2, p3);   // row g+8
        }
        rs0 += __shfl_xor_sync(0xffffffffu, rs0, 1);
        rs0 += __shfl_xor_sync(0xffffffffu, rs0, 2);
        rs1 += __shfl_xor_sync(0xffffffffu, rs1, 1);
        rs1 += __shfl_xor_sync(0xffffffffu, rs1, 2);
        l0 = l0*scl0 + rs0;
        l1 = l1*scl1 + rs1;

        // ---- O = O*scale + P @ V ----
        #pragma unroll
        for (int dt = 0; dt < 8; dt++) {
            oacc[dt][0] *= scl0; oacc[dt][1] *= scl0;
            oacc[dt][2] *= scl1; oacc[dt][3] *= scl1;
        }
        uint32_t vb = sV + (buf*64*KVW)*4;
        #pragma unroll
        for (int ks = 0; ks < 4; ks++) {
            uint32_t bv[4][4];
            #pragma unroll
            for (int j = 0; j < 4; j++)
                ldsm4t(bv[j], vb + (ks*16*KVW + j*8)*4 + vfix);
            #pragma unroll
            for (int dt = 0; dt < 8; dt++)
                mma_f16(oacc[dt], pf[ks], &bv[dt >> 1][(dt & 1)*2]);
        }
    }

    // epilogue
    float inv0 = 1.f / l0, inv1 = 1.f / l1;
    int r0 = q0 + qbase + g;
    #pragma unroll
    for (int dt = 0; dt < 8; dt++) {
        int dd = dt*8 + 2*tig;
        *(uint32_t*)&Y[((size_t) r0     *B_ + b)*C_ + hoff + dd] =
            f2h2(oacc[dt][0]*inv0, oacc[dt][1]*inv0);
        *(uint32_t*)&Y[((size_t)(r0 + 8)*B_ + b)*C_ + hoff + dd] =
            f2h2(oacc[dt][2]*inv1, oacc[dt][3]*inv1);
    }
}

// ---------------- launch -----------------------------------------------------
extern "C" void kernel_launch(void* const* d_in, const int* in_sizes, int n_in,
                              void* d_out, int out_size) {
    const float* x     = (const float*)d_in[0];
    const float* c     = (const float*)d_in[1];
    const int*   pmask = (const int*)  d_in[2];
    const float* audio = (const float*)d_in[3];
    const int*   amask = (const int*)  d_in[4];
    const float* w_ada = (const float*)d_in[5];
    const float* b_ada = (const float*)d_in[6];
    const float* wq = (const float*)d_in[7];   const float* bq = (const float*)d_in[8];
    const float* wk = (const float*)d_in[9];   const float* bk = (const float*)d_in[10];
    const float* wv = (const float*)d_in[11];  const float* bv = (const float*)d_in[12];
    const float* wo = (const float*)d_in[13];  const float* bo = (const float*)d_in[14];
    const float* cwq = (const float*)d_in[15]; const float* cbq = (const float*)d_in[16];
    const float* cwk = (const float*)d_in[17]; const float* cbk = (const float*)d_in[18];
    const float* cwv = (const float*)d_in[19]; const float* cbv = (const float*)d_in[20];
    const float* cwo = (const float*)d_in[21]; const float* cbo = (const float*)d_in[22];
    const float* w1 = (const float*)d_in[23];  const float* b1 = (const float*)d_in[24];
    const float* w2 = (const float*)d_in[25];  const float* b2 = (const float*)d_in[26];
    float* out = (float*)d_out;

    float  *modp;
    __half *whp, *ahp, *lnp, *qkvp, *yp, *hp;
    cudaGetSymbolAddress((void**)&modp, g_mod);
    cudaGetSymbolAddress((void**)&whp,  g_wh);
    cudaGetSymbolAddress((void**)&ahp,  g_ah);
    cudaGetSymbolAddress((void**)&lnp,  g_lnh);
    cudaGetSymbolAddress((void**)&qkvp, g_qkv);
    cudaGetSymbolAddress((void**)&yp,   g_yh);
    cudaGetSymbolAddress((void**)&hp,   g_hh);

    cudaFuncSetAttribute(fattn_k, cudaFuncAttributeMaxDynamicSharedMemorySize, ATT_SMEM);

    dim3 gQKV(24, 64);
    dim3 gC(8, 64);
    dim3 gM(32, 64);
    dim3 gA(T_/128, H_, B_);

    copy_k<<<(R_*C_)/1024, 256>>>(x, out);
    mod_k<<<SIXC/256, 256>>>(c, w_ada, b_ada, modp);
    f2h8_k<<<dim3((C_*C_)/2048, 8), 256>>>(wq, wk, wv, wo, cwq, cwk, cwv, cwo, whp);
    f2h_k<<<(C_*M_)/2048, 256>>>(w1, whp + WOFF_W1);
    f2h_k<<<(M_*C_)/2048, 256>>>(w2, whp + WOFF_W2);
    f2h_k<<<(R_*C_)/2048, 256>>>(audio, ahp);

    // ---- self attention ----
    ln_mod_k<<<R_, 256>>>(out, modp, 0, C_, lnp);
    hgemm_qkv_k<<<gQKV, 256>>>(lnp, lnp, whp, bq, bk, bv, qkvp, WOFF_Q, C_);
    fattn_k<<<gA, 256, ATT_SMEM>>>(qkvp, pmask, yp, T_);
    hgemm_k<2, float><<<gC, 256>>>(yp, whp + WOFF_O, bo, out, modp + 2*C_, C_, C_);

    // ---- cross attention (reuses msa shift/scale/gate) ----
    ln_mod_k<<<R_, 256>>>(out, modp, 0, C_, lnp);
    hgemm_qkv_k<<<gQKV, 256>>>(lnp, ahp, whp, cbq, cbk, cbv, qkvp, WOFF_CQ, C_);
    fattn_k<<<gA, 256, ATT_SMEM>>>(qkvp, amask, yp, TA_);
    hgemm_k<2, float><<<gC, 256>>>(yp, whp + WOFF_CO, cbo, out, modp + 2*C_, C_, C_);

    // ---- MLP ----
    ln_mod_k<<<R_, 256>>>(out, modp, 3*C_, 4*C_, lnp);
    hgemm_k<1, __half><<<gM, 256>>>(lnp, whp + WOFF_W1, b1, hp, nullptr, C_, M_);
    hgemm_k<2, float><<<gC, 256>>>(hp, whp + WOFF_W2, b2, out, modp + 5*C_, M_, C_);
}

// round 11
// speedup vs baseline: 1.3729x; 1.1175x over previous
#include <cuda_runtime.h>
#include <cuda_fp16.h>
#include <math.h>
#include <stdint.h>

#define T_  1024
#define B_  8
#define C_  1024
#define H_  16
#define D_  64
#define M_  4096
#define TA_ 1024
#define R_  (T_*B_)
#define SIXC (6*C_)

// ---------------- scratch (device globals) -----------------------------------
__device__ float  g_mod[B_*SIXC];
__device__ __half g_wh [16*1024*1024];     // packed fp16 weights [K,N]
__device__ __half g_ah [(size_t)R_*C_];    // audio fp16
__device__ __half g_lnh[(size_t)R_*C_];    // ln+modulate fp16
__device__ __half g_qkv[(size_t)R_*3*C_];  // merged q|k|v fp16, row stride 3C
__device__ __half g_yh [(size_t)R_*C_];    // attention out fp16
__device__ __half g_hh [(size_t)R_*M_];    // mlp hidden fp16

#define WOFF_Q   (0)
#define WOFF_O   (3*1024*1024)
#define WOFF_CQ  (4*1024*1024)
#define WOFF_CO  (7*1024*1024)
#define WOFF_W1  (8*1024*1024)
#define WOFF_W2  (12*1024*1024)

// ---------------- helpers ----------------------------------------------------
__device__ __forceinline__ float gelu_tanh(float x) {
    float x3 = x*x*x;
    return 0.5f*x*(1.f + tanhf(0.7978845608028654f*(x + 0.044715f*x3)));
}
__device__ __forceinline__ uint32_t f2h2(float lo, float hi) {
    __half2 h = __floats2half2_rn(lo, hi);
    return *reinterpret_cast<uint32_t*>(&h);
}
__device__ __forceinline__ void mma_f16(float* d, const uint32_t* a, const uint32_t* b) {
    asm volatile(
        "mma.sync.aligned.m16n8k16.row.col.f32.f16.f16.f32 "
        "{%0,%1,%2,%3}, {%4,%5,%6,%7}, {%8,%9}, {%0,%1,%2,%3};\n"
        : "+f"(d[0]), "+f"(d[1]), "+f"(d[2]), "+f"(d[3])
        : "r"(a[0]), "r"(a[1]), "r"(a[2]), "r"(a[3]), "r"(b[0]), "r"(b[1]));
}
__device__ __forceinline__ void ldsm4(uint32_t* r, uint32_t addr) {
    asm volatile("ldmatrix.sync.aligned.m8n8.x4.shared.b16 {%0,%1,%2,%3}, [%4];"
        : "=r"(r[0]), "=r"(r[1]), "=r"(r[2]), "=r"(r[3]) : "r"(addr));
}
__device__ __forceinline__ void ldsm4t(uint32_t* r, uint32_t addr) {
    asm volatile("ldmatrix.sync.aligned.m8n8.x4.trans.shared.b16 {%0,%1,%2,%3}, [%4];"
        : "=r"(r[0]), "=r"(r[1]), "=r"(r[2]), "=r"(r[3]) : "r"(addr));
}
__device__ __forceinline__ void cpa16(uint32_t dst, const void* src) {
    asm volatile("cp.async.ca.shared.global [%0], [%1], 16;\n" :: "r"(dst), "l"(src));
}
__device__ __forceinline__ void cpa_commit() { asm volatile("cp.async.commit_group;\n"); }
__device__ __forceinline__ void cpa_wait1()  { asm volatile("cp.async.wait_group 1;\n"); }
__device__ __forceinline__ void cpa_wait0()  { asm volatile("cp.async.wait_group 0;\n"); }

// ---------------- small utility kernels --------------------------------------
__global__ void copy_k(const float* __restrict__ in, float* __restrict__ out) {
    int i = blockIdx.x*blockDim.x + threadIdx.x;
    ((float4*)out)[i] = ((const float4*)in)[i];
}
// fused conversion of the 8 CxC weight matrices; grid (512, 8)
__global__ void f2h8_k(const float* __restrict__ p0, const float* __restrict__ p1,
                       const float* __restrict__ p2, const float* __restrict__ p3,
                       const float* __restrict__ p4, const float* __restrict__ p5,
                       const float* __restrict__ p6, const float* __restrict__ p7,
                       __half* __restrict__ out) {
    const float* src;
    switch (blockIdx.y) {
        case 0: src = p0; break; case 1: src = p1; break;
        case 2: src = p2; break; case 3: src = p3; break;
        case 4: src = p4; break; case 5: src = p5; break;
        case 6: src = p6; break; default: src = p7; break;
    }
    int i = (blockIdx.x*256 + threadIdx.x)*8;
    float4 a = *(const float4*)&src[i];
    float4 b = *(const float4*)&src[i+4];
    *(uint4*)&out[(size_t)blockIdx.y*(C_*C_) + i] =
        make_uint4(f2h2(a.x,a.y), f2h2(a.z,a.w), f2h2(b.x,b.y), f2h2(b.z,b.w));
}
// fused conversion: y0 w1(4M), y1 w2(4M), y2/y3 audio halves; grid (2048, 4)
__global__ void f2hm_k(const float* __restrict__ w1, const float* __restrict__ w2,
                       const float* __restrict__ audio,
                       __half* __restrict__ wh, __half* __restrict__ ah) {
    const float* src; __half* dst;
    switch (blockIdx.y) {
        case 0: src = w1; dst = wh + WOFF_W1; break;
        case 1: src = w2; dst = wh + WOFF_W2; break;
        case 2: src = audio; dst = ah; break;
        default: src = audio + 4*1024*1024; dst = ah + 4*1024*1024; break;
    }
    int i = (blockIdx.x*256 + threadIdx.x)*8;
    float4 a = *(const float4*)&src[i];
    float4 b = *(const float4*)&src[i+4];
    *(uint4*)&dst[i] = make_uint4(f2h2(a.x,a.y), f2h2(a.z,a.w),
                                  f2h2(b.x,b.y), f2h2(b.z,b.w));
}

// ---------------- mod = silu(c) @ w_ada + b_ada ------------------------------
__global__ void mod_k(const float* __restrict__ c, const float* __restrict__ w,
                      const float* __restrict__ bias, float* __restrict__ mod) {
    __shared__ float sc[B_][C_];
    int tid = threadIdx.x;
    for (int i = tid; i < B_*C_; i += 256) {
        float v = c[i];
        sc[i>>10][i&1023] = v / (1.f + __expf(-v));
    }
    __syncthreads();
    int col = blockIdx.x*256 + tid;
    float acc[B_];
    #pragma unroll
    for (int b = 0; b < B_; b++) acc[b] = 0.f;
    for (int k = 0; k < C_; k++) {
        float wv = w[(size_t)k*SIXC + col];
        #pragma unroll
        for (int b = 0; b < B_; b++) acc[b] += sc[b][k]*wv;
    }
    float bb = bias[col];
    #pragma unroll
    for (int b = 0; b < B_; b++) mod[b*SIXC + col] = acc[b] + bb;
}

// ---------------- LN (no affine) + modulate -> fp16 --------------------------
__global__ void ln_mod_k(const float* __restrict__ x, const float* __restrict__ mod,
                         int shiftOff, int scaleOff, __half* __restrict__ out) {
    int row = blockIdx.x;
    int b   = row & (B_-1);
    int tid = threadIdx.x;
    const float* xr = x + (size_t)row*C_;
    float4 v = *(const float4*)&xr[tid*4];
    float s  = v.x + v.y + v.z + v.w;
    float s2 = v.x*v.x + v.y*v.y + v.z*v.z + v.w*v.w;
    #pragma unroll
    for (int o = 16; o; o >>= 1) {
        s  += __shfl_xor_sync(0xffffffffu, s,  o);
        s2 += __shfl_xor_sync(0xffffffffu, s2, o);
    }
    __shared__ float red[2][8];
    int w = tid >> 5, ln = tid & 31;
    if (ln == 0) { red[0][w] = s; red[1][w] = s2; }
    __syncthreads();
    s = 0.f; s2 = 0.f;
    #pragma unroll
    for (int i = 0; i < 8; i++) { s += red[0][i]; s2 += red[1][i]; }
    float mu   = s * (1.f/C_);
    float var  = s2 * (1.f/C_) - mu*mu;
    float rstd = rsqrtf(var + 1e-6f);
    const float* sh = mod + b*SIXC + shiftOff + tid*4;
    const float* sc = mod + b*SIXC + scaleOff + tid*4;
    float4 shv = *(const float4*)sh;
    float4 scv = *(const float4*)sc;
    float m0 = (v.x-mu)*rstd*(1.f+scv.x) + shv.x;
    float m1 = (v.y-mu)*rstd*(1.f+scv.y) + shv.y;
    float m2 = (v.z-mu)*rstd*(1.f+scv.z) + shv.z;
    float m3 = (v.w-mu)*rstd*(1.f+scv.w) + shv.w;
    *(uint2*)&out[(size_t)row*C_ + tid*4] = make_uint2(f2h2(m0,m1), f2h2(m2,m3));
}

// ---------------- fp16 GEMM 128x128, BK=32, 128 thr, warp tile 64x64 ---------
// As: per 16-k slice [row][8 u32], row stride SAW=12 u32 (48B)
// Bs: per 16-k slice [k][64 u32], row stride SBW=68 u32 (272B)
#define SAW 12
#define SBW 68
#define ABUF (2*128*SAW)
#define BBUF (2*16*SBW)

template<int EPI, typename OT>
__device__ __forceinline__ void gemm_body(
    uint32_t* AsS, uint32_t* BsS,
    const __half* __restrict__ A, const __half* __restrict__ W,
    const float* __restrict__ bias, OT* __restrict__ out,
    const float* __restrict__ gate,
    int K, int N, int row0, int col0, size_t ostride, int ocol0)
{
    int tid  = threadIdx.x;
    int lane = tid & 31, wid = tid >> 5;          // 4 warps
    int g    = lane >> 2, tig = lane & 3;
    int wm   = wid >> 1, wn = wid & 1;            // warp tile 64m x 64n

    uint32_t sA0 = (uint32_t)__cvta_generic_to_shared(AsS);
    uint32_t sB0 = (uint32_t)__cvta_generic_to_shared(BsS);

    float acc[4][8][4];
    #pragma unroll
    for (int i = 0; i < 4; i++)
        #pragma unroll
        for (int j = 0; j < 8; j++)
            #pragma unroll
            for (int q = 0; q < 4; q++) acc[i][j][q] = 0.f;

    // 128 threads: A chunk 512 x 16B, B chunk 512 x 16B -> 4+4 cpa16/thread
    auto load_chunk = [&](int k0, int bf) {
        #pragma unroll
        for (int p = 0; p < 4; p++) {
            int idx = tid + p*128;
            int row = idx >> 2, q = idx & 3, ks = q >> 1, hs = q & 1;
            const __half* src = A + (size_t)(row0 + row)*K + k0 + ks*16 + hs*8;
            uint32_t dst = sA0 + (bf*ABUF + ks*128*SAW + row*SAW + hs*4)*4;
            cpa16(dst, src);
        }
        #pragma unroll
        for (int p = 0; p < 4; p++) {
            int idx = tid + p*128;
            int kr = idx >> 4, nc = idx & 15;
            const __half* src = W + (size_t)(k0 + kr)*N + col0 + nc*8;
            uint32_t dst = sB0 + (bf*BBUF + (kr>>4)*16*SBW + (kr&15)*SBW + nc*4)*4;
            cpa16(dst, src);
        }
        cpa_commit();
    };

    load_chunk(0, 0);

    int buf = 0;
    int nchunk = K >> 5;
    for (int ch = 0; ch < nchunk; ch++) {
        bool more = (ch + 1 < nchunk);
        if (more) { load_chunk((ch + 1)*32, buf ^ 1); cpa_wait1(); }
        else      { cpa_wait0(); }
        __syncthreads();

        #pragma unroll
        for (int ks = 0; ks < 2; ks++) {
            uint32_t sA = sA0 + (buf*ABUF + ks*128*SAW)*4;
            uint32_t sB = sB0 + (buf*BBUF + ks*16*SBW)*4;
            uint32_t af[4][4];
            #pragma unroll
            for (int mt = 0; mt < 4; mt++) {
                uint32_t addr = sA + ((wm*64 + mt*16 + (lane & 15))*SAW + ((lane >> 4) << 2))*4;
                ldsm4(af[mt], addr);
            }
            uint32_t bq[4][4];   // 4 ldsm4t cover warp's 64 n-cols (8 n-tiles)
            #pragma unroll
            for (int hf = 0; hf < 4; hf++) {
                uint32_t addr = sB + ((lane & 15)*SBW + (wn*32 + hf*8) + ((lane >> 4) << 2))*4;
                ldsm4t(bq[hf], addr);
            }
            #pragma unroll
            for (int mt = 0; mt < 4; mt++)
                #pragma unroll
                for (int nt = 0; nt < 8; nt++)
                    mma_f16(acc[mt][nt], af[mt], &bq[nt >> 1][(nt & 1)*2]);
        }
        __syncthreads();
        buf ^= 1;
    }

    #pragma unroll
    for (int mt = 0; mt < 4; mt++) {
        int rbase = row0 + wm*64 + mt*16 + g;
        #pragma unroll
        for (int half = 0; half < 2; half++) {
            int rr = rbase + 8*half;
            int bb = rr & (B_-1);
            OT* orow = out + (size_t)rr*ostride + ocol0;
            #pragma unroll
            for (int nt = 0; nt < 8; nt++) {
                int cl = col0 + wn*64 + nt*8 + 2*tig;
                float v0 = acc[mt][nt][2*half + 0] + bias[cl];
                float v1 = acc[mt][nt][2*half + 1] + bias[cl+1];
                if (EPI == 2) {
                    float* fr = (float*)orow;
                    fr[cl]   += gate[bb*SIXC + cl  ]*v0;
                    fr[cl+1] += gate[bb*SIXC + cl+1]*v1;
                } else if (EPI == 1) {
                    *(uint32_t*)&orow[cl] = f2h2(gelu_tanh(v0), gelu_tanh(v1));
                } else {
                    *(uint32_t*)&orow[cl] = f2h2(v0, v1);
                }
            }
        }
    }
}

template<int EPI, typename OT>
__global__ void __launch_bounds__(128, 2)
hgemm_k(const __half* __restrict__ A, const __half* __restrict__ W,
        const float* __restrict__ bias, OT* __restrict__ out,
        const float* __restrict__ gate, int K, int N) {
    __shared__ __align__(16) uint32_t As[2*ABUF];
    __shared__ __align__(16) uint32_t Bs[2*BBUF];
    gemm_body<EPI, OT>(As, Bs, A, W, bias, out, gate, K, N,
                       blockIdx.y*128, blockIdx.x*128, N, 0);
}

__global__ void __launch_bounds__(128, 2)
hgemm_qkv_k(const __half* __restrict__ A0, const __half* __restrict__ A12,
            const __half* __restrict__ Wbase,
            const float* __restrict__ b0, const float* __restrict__ b1,
            const float* __restrict__ b2,
            __half* __restrict__ out, int woff0, int K) {
    __shared__ __align__(16) uint32_t As[2*ABUF];
    __shared__ __align__(16) uint32_t Bs[2*BBUF];
    int sel = blockIdx.x >> 3;
    int nb  = blockIdx.x & 7;
    const __half* A    = (sel == 0) ? A0 : A12;
    const __half* W    = Wbase + woff0 + sel*(C_*C_);
    const float* bias  = (sel == 0) ? b0 : (sel == 1) ? b1 : b2;
    gemm_body<0, __half>(As, Bs, A, W, bias, out, nullptr, K, C_,
                         blockIdx.y*128, nb*128, 3*C_, sel*C_);
}

// ---------------- register-resident fp16 flash attention (round-10) ----------
#define KVW 36
#define ATT_SMEM ((128*KVW + 4*64*KVW)*4 + 1024*4)
__global__ void __launch_bounds__(256, 2)
fattn_k(const __half* __restrict__ QKV, const int* __restrict__ mask,
        __half* __restrict__ Y, int Tk) {
    extern __shared__ uint32_t smu[];
    uint32_t* Qs = smu;
    uint32_t* Ks = Qs + 128*KVW;
    uint32_t* Vs = Ks + 2*64*KVW;
    int*      Msk = (int*)(Vs + 2*64*KVW);

    int tid  = threadIdx.x;
    int lane = tid & 31, wid = tid >> 5;
    int g    = lane >> 2, tig = lane & 3;
    int qbase = wid*16;
    int q0 = blockIdx.x*128, h = blockIdx.y, b = blockIdx.z;
    size_t hoff = (size_t)h*D_;
    const int RS = 3*C_;
    const __half* Kp = QKV + C_;
    const __half* Vp = QKV + 2*C_;

    uint32_t sQ = (uint32_t)__cvta_generic_to_shared(Qs);
    uint32_t sK = (uint32_t)__cvta_generic_to_shared(Ks);
    uint32_t sV = (uint32_t)__cvta_generic_to_shared(Vs);

    for (int i = tid; i < (Tk >> 2); i += 256)
        *(int4*)&Msk[i*4] = *(const int4*)&mask[(size_t)b*Tk + i*4];

    #pragma unroll
    for (int p = 0; p < 4; p++) {
        int idx = tid + p*256;
        int r = idx >> 3, c8 = idx & 7;
        *(uint4*)&Qs[r*KVW + c8*4] =
            *(const uint4*)&QKV[((size_t)(q0+r)*B_ + b)*RS + hoff + c8*8];
    }

    auto load_kv = [&](int k0, int bf) {
        #pragma unroll
        for (int p = 0; p < 2; p++) {
            int idx = tid + p*256;
            int r = idx >> 3, c8 = idx & 7;
            size_t gi = ((size_t)(k0+r)*B_ + b)*RS + hoff + c8*8;
            uint32_t off = (bf*64*KVW + r*KVW + c8*4)*4;
            cpa16(sK + off, Kp + gi);
            cpa16(sV + off, Vp + gi);
        }
        cpa_commit();
    };
    load_kv(0, 0);

    float m0 = -1e30f, m1 = -1e30f, l0 = 0.f, l1 = 0.f;
    float oacc[8][4];
    #pragma unroll
    for (int i = 0; i < 8; i++)
        #pragma unroll
        for (int j = 0; j < 4; j++) oacc[i][j] = 0.f;

    uint32_t qaddr = sQ + ((qbase + (lane & 15))*KVW + ((lane >> 4) << 2))*4;
    uint32_t vfix  = ((lane & 15)*KVW + ((lane >> 4) << 2))*4;

    int ntile = Tk >> 6;
    for (int kt = 0; kt < ntile; kt++) {
        int buf = kt & 1;
        cpa_wait0();
        __syncthreads();
        if (kt + 1 < ntile) load_kv((kt + 1)*64, buf ^ 1);

        const uint32_t* Ksb = Ks + buf*64*KVW;
        float sacc[8][4];
        #pragma unroll
        for (int i = 0; i < 8; i++)
            #pragma unroll
            for (int j = 0; j < 4; j++) sacc[i][j] = 0.f;
        #pragma unroll
        for (int ks = 0; ks < 4; ks++) {
            uint32_t qf[4];
            ldsm4(qf, qaddr + ks*32);
            #pragma unroll
            for (int nt = 0; nt < 8; nt++) {
                uint32_t bf[2];
                const uint32_t* kp = &Ksb[(nt*8 + g)*KVW + ks*8 + tig];
                bf[0] = kp[0]; bf[1] = kp[4];
                mma_f16(sacc[nt], qf, bf);
            }
        }

        float mx0 = -1e30f, mx1 = -1e30f;
        #pragma unroll
        for (int nt = 0; nt < 8; nt++) {
            int2 mm = *(const int2*)&Msk[kt*64 + nt*8 + 2*tig];
            sacc[nt][0] = mm.x ? -1e30f : sacc[nt][0]*0.125f;
            sacc[nt][1] = mm.y ? -1e30f : sacc[nt][1]*0.125f;
            sacc[nt][2] = mm.x ? -1e30f : sacc[nt][2]*0.125f;
            sacc[nt][3] = mm.y ? -1e30f : sacc[nt][3]*0.125f;
            mx0 = fmaxf(mx0, fmaxf(sacc[nt][0], sacc[nt][1]));
            mx1 = fmaxf(mx1, fmaxf(sacc[nt][2], sacc[nt][3]));
        }
        mx0 = fmaxf(mx0, __shfl_xor_sync(0xffffffffu, mx0, 1));
        mx0 = fmaxf(mx0, __shfl_xor_sync(0xffffffffu, mx0, 2));
        mx1 = fmaxf(mx1, __shfl_xor_sync(0xffffffffu, mx1, 1));
        mx1 = fmaxf(mx1, __shfl_xor_sync(0xffffffffu, mx1, 2));
        float mn0 = fmaxf(m0, mx0), mn1 = fmaxf(m1, mx1);
        float scl0 = __expf(m0 - mn0), scl1 = __expf(m1 - mn1);
        m0 = mn0; m1 = mn1;

        uint32_t pf[4][4];
        float rs0 = 0.f, rs1 = 0.f;
        #pragma unroll
        for (int nt = 0; nt < 8; nt++) {
            float p0 = (sacc[nt][0] > -1e29f) ? __expf(sacc[nt][0] - mn0) : 0.f;
            float p1 = (sacc[nt][1] > -1e29f) ? __expf(sacc[nt][1] - mn0) : 0.f;
            float p2 = (sacc[nt][2] > -1e29f) ? __expf(sacc[nt][2] - mn1) : 0.f;
            float p3 = (sacc[nt][3] > -1e29f) ? __expf(sacc[nt][3] - mn1) : 0.f;
            rs0 += p0 + p1; rs1 += p2 + p3;
            pf[nt >> 1][0 + 2*(nt & 1)] = f2h2(p0, p1);
            pf[nt >> 1][1 + 2*(nt & 1)] = f2h2(p2, p3);
        }
        rs0 += __shfl_xor_sync(0xffffffffu, rs0, 1);
        rs0 += __shfl_xor_sync(0xffffffffu, rs0, 2);
        rs1 += __shfl_xor_sync(0xffffffffu, rs1, 1);
        rs1 += __shfl_xor_sync(0xffffffffu, rs1, 2);
        l0 = l0*scl0 + rs0;
        l1 = l1*scl1 + rs1;

        #pragma unroll
        for (int dt = 0; dt < 8; dt++) {
            oacc[dt][0] *= scl0; oacc[dt][1] *= scl0;
            oacc[dt][2] *= scl1; oacc[dt][3] *= scl1;
        }
        uint32_t vb = sV + (buf*64*KVW)*4;
        #pragma unroll
        for (int ks = 0; ks < 4; ks++) {
            uint32_t bv[4][4];
            #pragma unroll
            for (int j = 0; j < 4; j++)
                ldsm4t(bv[j], vb + (ks*16*KVW + j*8)*4 + vfix);
            #pragma unroll
            for (int dt = 0; dt < 8; dt++)
                mma_f16(oacc[dt], pf[ks], &bv[dt >> 1][(dt & 1)*2]);
        }
    }

    float inv0 = 1.f / l0, inv1 = 1.f / l1;
    int r0 = q0 + qbase + g;
    #pragma unroll
    for (int dt = 0; dt < 8; dt++) {
        int dd = dt*8 + 2*tig;
        *(uint32_t*)&Y[((size_t) r0     *B_ + b)*C_ + hoff + dd] =
            f2h2(oacc[dt][0]*inv0, oacc[dt][1]*inv0);
        *(uint32_t*)&Y[((size_t)(r0 + 8)*B_ + b)*C_ + hoff + dd] =
            f2h2(oacc[dt][2]*inv1, oacc[dt][3]*inv1);
    }
}

// ---------------- launch -----------------------------------------------------
extern "C" void kernel_launch(void* const* d_in, const int* in_sizes, int n_in,
                              void* d_out, int out_size) {
    const float* x     = (const float*)d_in[0];
    const float* c     = (const float*)d_in[1];
    const int*   pmask = (const int*)  d_in[2];
    const float* audio = (const float*)d_in[3];
    const int*   amask = (const int*)  d_in[4];
    const float* w_ada = (const float*)d_in[5];
    const float* b_ada = (const float*)d_in[6];
    const float* wq = (const float*)d_in[7];   const float* bq = (const float*)d_in[8];
    const float* wk = (const float*)d_in[9];   const float* bk = (const float*)d_in[10];
    const float* wv = (const float*)d_in[11];  const float* bv = (const float*)d_in[12];
    const float* wo = (const float*)d_in[13];  const float* bo = (const float*)d_in[14];
    const float* cwq = (const float*)d_in[15]; const float* cbq = (const float*)d_in[16];
    const float* cwk = (const float*)d_in[17]; const float* cbk = (const float*)d_in[18];
    const float* cwv = (const float*)d_in[19]; const float* cbv = (const float*)d_in[20];
    const float* cwo = (const float*)d_in[21]; const float* cbo = (const float*)d_in[22];
    const float* w1 = (const float*)d_in[23];  const float* b1 = (const float*)d_in[24];
    const float* w2 = (const float*)d_in[25];  const float* b2 = (const float*)d_in[26];
    float* out = (float*)d_out;

    float  *modp;
    __half *whp, *ahp, *lnp, *qkvp, *yp, *hp;
    cudaGetSymbolAddress((void**)&modp, g_mod);
    cudaGetSymbolAddress((void**)&whp,  g_wh);
    cudaGetSymbolAddress((void**)&ahp,  g_ah);
    cudaGetSymbolAddress((void**)&lnp,  g_lnh);
    cudaGetSymbolAddress((void**)&qkvp, g_qkv);
    cudaGetSymbolAddress((void**)&yp,   g_yh);
    cudaGetSymbolAddress((void**)&hp,   g_hh);

    cudaFuncSetAttribute(fattn_k, cudaFuncAttributeMaxDynamicSharedMemorySize, ATT_SMEM);

    dim3 gQKV(24, 64);
    dim3 gC(8, 64);
    dim3 gM(32, 64);
    dim3 gA(T_/128, H_, B_);

    copy_k<<<(R_*C_)/1024, 256>>>(x, out);
    mod_k<<<SIXC/256, 256>>>(c, w_ada, b_ada, modp);
    f2h8_k<<<dim3((C_*C_)/2048, 8), 256>>>(wq, wk, wv, wo, cwq, cwk, cwv, cwo, whp);
    f2hm_k<<<dim3(2048, 4), 256>>>(w1, w2, audio, whp, ahp);

    // ---- self attention ----
    ln_mod_k<<<R_, 256>>>(out, modp, 0, C_, lnp);
    hgemm_qkv_k<<<gQKV, 128>>>(lnp, lnp, whp, bq, bk, bv, qkvp, WOFF_Q, C_);
    fattn_k<<<gA, 256, ATT_SMEM>>>(qkvp, pmask, yp, T_);
    hgemm_k<2, float><<<gC, 128>>>(yp, whp + WOFF_O, bo, out, modp + 2*C_, C_, C_);

    // ---- cross attention (reuses msa shift/scale/gate) ----
    ln_mod_k<<<R_, 256>>>(out, modp, 0, C_, lnp);
    hgemm_qkv_k<<<gQKV, 128>>>(lnp, ahp, whp, cbq, cbk, cbv, qkvp, WOFF_CQ, C_);
    fattn_k<<<gA, 256, ATT_SMEM>>>(qkvp, amask, yp, TA_);
    hgemm_k<2, float><<<gC, 128>>>(yp, whp + WOFF_CO, cbo, out, modp + 2*C_, C_, C_);

    // ---- MLP ----
    ln_mod_k<<<R_, 256>>>(out, modp, 3*C_, 4*C_, lnp);
    hgemm_k<1, __half><<<gM, 128>>>(lnp, whp + WOFF_W1, b1, hp, nullptr, C_, M_);
    hgemm_k<2, float><<<gC, 128>>>(hp, whp + WOFF_W2, b2, out, modp + 5*C_, M_, C_);
}

// round 12
// speedup vs baseline: 1.4750x; 1.0744x over previous
#include <cuda_runtime.h>
#include <cuda_fp16.h>
#include <math.h>
#include <stdint.h>

#define T_  1024
#define B_  8
#define C_  1024
#define H_  16
#define D_  64
#define M_  4096
#define TA_ 1024
#define R_  (T_*B_)
#define SIXC (6*C_)

// ---------------- scratch (device globals) -----------------------------------
__device__ float  g_mod[B_*SIXC];
__device__ __half g_wh [16*1024*1024];     // packed fp16 weights [K,N]
__device__ __half g_ah [(size_t)R_*C_];    // audio fp16
__device__ __half g_lnh[(size_t)R_*C_];    // ln+modulate fp16
__device__ __half g_qkv [(size_t)R_*3*C_]; // self q|k|v fp16, row stride 3C
__device__ __half g_qkv2[(size_t)R_*3*C_]; // cross q|k|v fp16, row stride 3C
__device__ __half g_yh [(size_t)R_*C_];    // attention out fp16
__device__ __half g_hh [(size_t)R_*M_];    // mlp hidden fp16

#define WOFF_Q   (0)
#define WOFF_O   (3*1024*1024)
#define WOFF_CQ  (4*1024*1024)
#define WOFF_CO  (7*1024*1024)
#define WOFF_W1  (8*1024*1024)
#define WOFF_W2  (12*1024*1024)

// ---------------- side stream + events (created once at load) ----------------
static cudaStream_t g_s1;
static cudaEvent_t  g_evFork, g_evConv, g_evKV;
struct _StreamInit {
    _StreamInit() {
        cudaStreamCreateWithFlags(&g_s1, cudaStreamNonBlocking);
        cudaEventCreateWithFlags(&g_evFork, cudaEventDisableTiming);
        cudaEventCreateWithFlags(&g_evConv, cudaEventDisableTiming);
        cudaEventCreateWithFlags(&g_evKV,   cudaEventDisableTiming);
    }
};
static _StreamInit _stream_init;

// ---------------- helpers ----------------------------------------------------
__device__ __forceinline__ float gelu_tanh(float x) {
    float x3 = x*x*x;
    return 0.5f*x*(1.f + tanhf(0.7978845608028654f*(x + 0.044715f*x3)));
}
__device__ __forceinline__ uint32_t f2h2(float lo, float hi) {
    __half2 h = __floats2half2_rn(lo, hi);
    return *reinterpret_cast<uint32_t*>(&h);
}
__device__ __forceinline__ void mma_f16(float* d, const uint32_t* a, const uint32_t* b) {
    asm volatile(
        "mma.sync.aligned.m16n8k16.row.col.f32.f16.f16.f32 "
        "{%0,%1,%2,%3}, {%4,%5,%6,%7}, {%8,%9}, {%0,%1,%2,%3};\n"
        : "+f"(d[0]), "+f"(d[1]), "+f"(d[2]), "+f"(d[3])
        : "r"(a[0]), "r"(a[1]), "r"(a[2]), "r"(a[3]), "r"(b[0]), "r"(b[1]));
}
__device__ __forceinline__ void ldsm4(uint32_t* r, uint32_t addr) {
    asm volatile("ldmatrix.sync.aligned.m8n8.x4.shared.b16 {%0,%1,%2,%3}, [%4];"
        : "=r"(r[0]), "=r"(r[1]), "=r"(r[2]), "=r"(r[3]) : "r"(addr));
}
__device__ __forceinline__ void ldsm4t(uint32_t* r, uint32_t addr) {
    asm volatile("ldmatrix.sync.aligned.m8n8.x4.trans.shared.b16 {%0,%1,%2,%3}, [%4];"
        : "=r"(r[0]), "=r"(r[1]), "=r"(r[2]), "=r"(r[3]) : "r"(addr));
}
__device__ __forceinline__ void cpa16(uint32_t dst, const void* src) {
    asm volatile("cp.async.ca.shared.global [%0], [%1], 16;\n" :: "r"(dst), "l"(src));
}
__device__ __forceinline__ void cpa_commit() { asm volatile("cp.async.commit_group;\n"); }
__device__ __forceinline__ void cpa_wait1()  { asm volatile("cp.async.wait_group 1;\n"); }
__device__ __forceinline__ void cpa_wait0()  { asm volatile("cp.async.wait_group 0;\n"); }

// ---------------- small utility kernels --------------------------------------
// fused conversion of the 8 CxC weight matrices; grid (512, 8)
__global__ void f2h8_k(const float* __restrict__ p0, const float* __restrict__ p1,
                       const float* __restrict__ p2, const float* __restrict__ p3,
                       const float* __restrict__ p4, const float* __restrict__ p5,
                       const float* __restrict__ p6, const float* __restrict__ p7,
                       __half* __restrict__ out) {
    const float* src;
    switch (blockIdx.y) {
        case 0: src = p0; break; case 1: src = p1; break;
        case 2: src = p2; break; case 3: src = p3; break;
        case 4: src = p4; break; case 5: src = p5; break;
        case 6: src = p6; break; default: src = p7; break;
    }
    int i = (blockIdx.x*256 + threadIdx.x)*8;
    float4 a = *(const float4*)&src[i];
    float4 b = *(const float4*)&src[i+4];
    *(uint4*)&out[(size_t)blockIdx.y*(C_*C_) + i] =
        make_uint4(f2h2(a.x,a.y), f2h2(a.z,a.w), f2h2(b.x,b.y), f2h2(b.z,b.w));
}
// fused conversion: y0 w1(4M), y1 w2(4M), y2/y3 audio halves; grid (2048, 4)
__global__ void f2hm_k(const float* __restrict__ w1, const float* __restrict__ w2,
                       const float* __restrict__ audio,
                       __half* __restrict__ wh, __half* __restrict__ ah) {
    const float* src; __half* dst;
    switch (blockIdx.y) {
        case 0: src = w1; dst = wh + WOFF_W1; break;
        case 1: src = w2; dst = wh + WOFF_W2; break;
        case 2: src = audio; dst = ah; break;
        default: src = audio + 4*1024*1024; dst = ah + 4*1024*1024; break;
    }
    int i = (blockIdx.x*256 + threadIdx.x)*8;
    float4 a = *(const float4*)&src[i];
    float4 b = *(const float4*)&src[i+4];
    *(uint4*)&dst[i] = make_uint4(f2h2(a.x,a.y), f2h2(a.z,a.w),
                                  f2h2(b.x,b.y), f2h2(b.z,b.w));
}

// ---------------- mod = silu(c) @ w_ada + b_ada ------------------------------
__global__ void mod_k(const float* __restrict__ c, const float* __restrict__ w,
                      const float* __restrict__ bias, float* __restrict__ mod) {
    __shared__ float sc[B_][C_];
    int tid = threadIdx.x;
    for (int i = tid; i < B_*C_; i += 256) {
        float v = c[i];
        sc[i>>10][i&1023] = v / (1.f + __expf(-v));
    }
    __syncthreads();
    int col = blockIdx.x*256 + tid;
    float acc[B_];
    #pragma unroll
    for (int b = 0; b < B_; b++) acc[b] = 0.f;
    for (int k = 0; k < C_; k++) {
        float wv = w[(size_t)k*SIXC + col];
        #pragma unroll
        for (int b = 0; b < B_; b++) acc[b] += sc[b][k]*wv;
    }
    float bb = bias[col];
    #pragma unroll
    for (int b = 0; b < B_; b++) mod[b*SIXC + col] = acc[b] + bb;
}

// ---------------- LN (no affine) + modulate -> fp16 --------------------------
// COPY!=0: also copy input row to res (residual init).
template<int COPY>
__global__ void ln_mod_k(const float* __restrict__ x, const float* __restrict__ mod,
                         int shiftOff, int scaleOff, __half* __restrict__ out,
                         float* __restrict__ res) {
    int row = blockIdx.x;
    int b   = row & (B_-1);
    int tid = threadIdx.x;
    const float* xr = x + (size_t)row*C_;
    float4 v = *(const float4*)&xr[tid*4];
    if (COPY) *(float4*)&res[(size_t)row*C_ + tid*4] = v;
    float s  = v.x + v.y + v.z + v.w;
    float s2 = v.x*v.x + v.y*v.y + v.z*v.z + v.w*v.w;
    #pragma unroll
    for (int o = 16; o; o >>= 1) {
        s  += __shfl_xor_sync(0xffffffffu, s,  o);
        s2 += __shfl_xor_sync(0xffffffffu, s2, o);
    }
    __shared__ float red[2][8];
    int w = tid >> 5, ln = tid & 31;
    if (ln == 0) { red[0][w] = s; red[1][w] = s2; }
    __syncthreads();
    s = 0.f; s2 = 0.f;
    #pragma unroll
    for (int i = 0; i < 8; i++) { s += red[0][i]; s2 += red[1][i]; }
    float mu   = s * (1.f/C_);
    float var  = s2 * (1.f/C_) - mu*mu;
    float rstd = rsqrtf(var + 1e-6f);
    const float* sh = mod + b*SIXC + shiftOff + tid*4;
    const float* sc = mod + b*SIXC + scaleOff + tid*4;
    float4 shv = *(const float4*)sh;
    float4 scv = *(const float4*)sc;
    float m0 = (v.x-mu)*rstd*(1.f+scv.x) + shv.x;
    float m1 = (v.y-mu)*rstd*(1.f+scv.y) + shv.y;
    float m2 = (v.z-mu)*rstd*(1.f+scv.z) + shv.z;
    float m3 = (v.w-mu)*rstd*(1.f+scv.w) + shv.w;
    *(uint2*)&out[(size_t)row*C_ + tid*4] = make_uint2(f2h2(m0,m1), f2h2(m2,m3));
}

// ---------------- fp16 GEMM 128x128, BK=32, 128 thr, warp tile 64x64 ---------
#define SAW 12
#define SBW 68
#define ABUF (2*128*SAW)
#define BBUF (2*16*SBW)

template<int EPI, typename OT>
__device__ __forceinline__ void gemm_body(
    uint32_t* AsS, uint32_t* BsS,
    const __half* __restrict__ A, const __half* __restrict__ W,
    const float* __restrict__ bias, OT* __restrict__ out,
    const float* __restrict__ gate,
    int K, int N, int row0, int col0, size_t ostride, int ocol0)
{
    int tid  = threadIdx.x;
    int lane = tid & 31, wid = tid >> 5;          // 4 warps
    int g    = lane >> 2, tig = lane & 3;
    int wm   = wid >> 1, wn = wid & 1;            // warp tile 64m x 64n

    uint32_t sA0 = (uint32_t)__cvta_generic_to_shared(AsS);
    uint32_t sB0 = (uint32_t)__cvta_generic_to_shared(BsS);

    float acc[4][8][4];
    #pragma unroll
    for (int i = 0; i < 4; i++)
        #pragma unroll
        for (int j = 0; j < 8; j++)
            #pragma unroll
            for (int q = 0; q < 4; q++) acc[i][j][q] = 0.f;

    auto load_chunk = [&](int k0, int bf) {
        #pragma unroll
        for (int p = 0; p < 4; p++) {
            int idx = tid + p*128;
            int row = idx >> 2, q = idx & 3, ks = q >> 1, hs = q & 1;
            const __half* src = A + (size_t)(row0 + row)*K + k0 + ks*16 + hs*8;
            uint32_t dst = sA0 + (bf*ABUF + ks*128*SAW + row*SAW + hs*4)*4;
            cpa16(dst, src);
        }
        #pragma unroll
        for (int p = 0; p < 4; p++) {
            int idx = tid + p*128;
            int kr = idx >> 4, nc = idx & 15;
            const __half* src = W + (size_t)(k0 + kr)*N + col0 + nc*8;
            uint32_t dst = sB0 + (bf*BBUF + (kr>>4)*16*SBW + (kr&15)*SBW + nc*4)*4;
            cpa16(dst, src);
        }
        cpa_commit();
    };

    load_chunk(0, 0);

    int buf = 0;
    int nchunk = K >> 5;
    for (int ch = 0; ch < nchunk; ch++) {
        bool more = (ch + 1 < nchunk);
        if (more) { load_chunk((ch + 1)*32, buf ^ 1); cpa_wait1(); }
        else      { cpa_wait0(); }
        __syncthreads();

        #pragma unroll
        for (int ks = 0; ks < 2; ks++) {
            uint32_t sA = sA0 + (buf*ABUF + ks*128*SAW)*4;
            uint32_t sB = sB0 + (buf*BBUF + ks*16*SBW)*4;
            uint32_t af[4][4];
            #pragma unroll
            for (int mt = 0; mt < 4; mt++) {
                uint32_t addr = sA + ((wm*64 + mt*16 + (lane & 15))*SAW + ((lane >> 4) << 2))*4;
                ldsm4(af[mt], addr);
            }
            uint32_t bq[4][4];
            #pragma unroll
            for (int hf = 0; hf < 4; hf++) {
                uint32_t addr = sB + ((lane & 15)*SBW + (wn*32 + hf*8) + ((lane >> 4) << 2))*4;
                ldsm4t(bq[hf], addr);
            }
            #pragma unroll
            for (int mt = 0; mt < 4; mt++)
                #pragma unroll
                for (int nt = 0; nt < 8; nt++)
                    mma_f16(acc[mt][nt], af[mt], &bq[nt >> 1][(nt & 1)*2]);
        }
        __syncthreads();
        buf ^= 1;
    }

    #pragma unroll
    for (int mt = 0; mt < 4; mt++) {
        int rbase = row0 + wm*64 + mt*16 + g;
        #pragma unroll
        for (int half = 0; half < 2; half++) {
            int rr = rbase + 8*half;
            int bb = rr & (B_-1);
            OT* orow = out + (size_t)rr*ostride + ocol0;
            #pragma unroll
            for (int nt = 0; nt < 8; nt++) {
                int cl = col0 + wn*64 + nt*8 + 2*tig;
                float v0 = acc[mt][nt][2*half + 0] + bias[cl];
                float v1 = acc[mt][nt][2*half + 1] + bias[cl+1];
                if (EPI == 2) {
                    float* fr = (float*)orow;
                    fr[cl]   += gate[bb*SIXC + cl  ]*v0;
                    fr[cl+1] += gate[bb*SIXC + cl+1]*v1;
                } else if (EPI == 1) {
                    *(uint32_t*)&orow[cl] = f2h2(gelu_tanh(v0), gelu_tanh(v1));
                } else {
                    *(uint32_t*)&orow[cl] = f2h2(v0, v1);
                }
            }
        }
    }
}

template<int EPI, typename OT>
__global__ void __launch_bounds__(128, 2)
hgemm_k(const __half* __restrict__ A, const __half* __restrict__ W,
        const float* __restrict__ bias, OT* __restrict__ out,
        const float* __restrict__ gate, int K, int N) {
    __shared__ __align__(16) uint32_t As[2*ABUF];
    __shared__ __align__(16) uint32_t Bs[2*BBUF];
    gemm_body<EPI, OT>(As, Bs, A, W, bias, out, gate, K, N,
                       blockIdx.y*128, blockIdx.x*128, N, 0);
}

// self q/k/v: grid (24,64); sel=0,1,2
__global__ void __launch_bounds__(128, 2)
hgemm_qkv_k(const __half* __restrict__ A, const __half* __restrict__ Wbase,
            const float* __restrict__ b0, const float* __restrict__ b1,
            const float* __restrict__ b2,
            __half* __restrict__ out, int woff0, int K) {
    __shared__ __align__(16) uint32_t As[2*ABUF];
    __shared__ __align__(16) uint32_t Bs[2*BBUF];
    int sel = blockIdx.x >> 3;
    int nb  = blockIdx.x & 7;
    const __half* W    = Wbase + woff0 + sel*(C_*C_);
    const float* bias  = (sel == 0) ? b0 : (sel == 1) ? b1 : b2;
    gemm_body<0, __half>(As, Bs, A, W, bias, out, nullptr, K, C_,
                         blockIdx.y*128, nb*128, 3*C_, sel*C_);
}
// cross k/v only (audio): grid (16,64); sel -> 1,2
__global__ void __launch_bounds__(128, 2)
hgemm_kv_k(const __half* __restrict__ A, const __half* __restrict__ Wbase,
           const float* __restrict__ b1, const float* __restrict__ b2,
           __half* __restrict__ out, int woff0, int K) {
    __shared__ __align__(16) uint32_t As[2*ABUF];
    __shared__ __align__(16) uint32_t Bs[2*BBUF];
    int sel = 1 + (blockIdx.x >> 3);
    int nb  = blockIdx.x & 7;
    const __half* W    = Wbase + woff0 + sel*(C_*C_);
    const float* bias  = (sel == 1) ? b1 : b2;
    gemm_body<0, __half>(As, Bs, A, W, bias, out, nullptr, K, C_,
                         blockIdx.y*128, nb*128, 3*C_, sel*C_);
}
// cross q only: grid (8,64)
__global__ void __launch_bounds__(128, 2)
hgemm_q_k(const __half* __restrict__ A, const __half* __restrict__ Wbase,
          const float* __restrict__ b0, __half* __restrict__ out,
          int woff0, int K) {
    __shared__ __align__(16) uint32_t As[2*ABUF];
    __shared__ __align__(16) uint32_t Bs[2*BBUF];
    gemm_body<0, __half>(As, Bs, A, Wbase + woff0, b0, out, nullptr, K, C_,
                         blockIdx.y*128, blockIdx.x*128, 3*C_, 0);
}

// ---------------- register-resident fp16 flash attention (round-10) ----------
#define KVW 36
#define ATT_SMEM ((128*KVW + 4*64*KVW)*4 + 1024*4)
__global__ void __launch_bounds__(256, 2)
fattn_k(const __half* __restrict__ QKV, const int* __restrict__ mask,
        __half* __restrict__ Y, int Tk) {
    extern __shared__ uint32_t smu[];
    uint32_t* Qs = smu;
    uint32_t* Ks = Qs + 128*KVW;
    uint32_t* Vs = Ks + 2*64*KVW;
    int*      Msk = (int*)(Vs + 2*64*KVW);

    int tid  = threadIdx.x;
    int lane = tid & 31, wid = tid >> 5;
    int g    = lane >> 2, tig = lane & 3;
    int qbase = wid*16;
    int q0 = blockIdx.x*128, h = blockIdx.y, b = blockIdx.z;
    size_t hoff = (size_t)h*D_;
    const int RS = 3*C_;
    const __half* Kp = QKV + C_;
    const __half* Vp = QKV + 2*C_;

    uint32_t sQ = (uint32_t)__cvta_generic_to_shared(Qs);
    uint32_t sK = (uint32_t)__cvta_generic_to_shared(Ks);
    uint32_t sV = (uint32_t)__cvta_generic_to_shared(Vs);

    for (int i = tid; i < (Tk >> 2); i += 256)
        *(int4*)&Msk[i*4] = *(const int4*)&mask[(size_t)b*Tk + i*4];

    #pragma unroll
    for (int p = 0; p < 4; p++) {
        int idx = tid + p*256;
        int r = idx >> 3, c8 = idx & 7;
        *(uint4*)&Qs[r*KVW + c8*4] =
            *(const uint4*)&QKV[((size_t)(q0+r)*B_ + b)*RS + hoff + c8*8];
    }

    auto load_kv = [&](int k0, int bf) {
        #pragma unroll
        for (int p = 0; p < 2; p++) {
            int idx = tid + p*256;
            int r = idx >> 3, c8 = idx & 7;
            size_t gi = ((size_t)(k0+r)*B_ + b)*RS + hoff + c8*8;
            uint32_t off = (bf*64*KVW + r*KVW + c8*4)*4;
            cpa16(sK + off, Kp + gi);
            cpa16(sV + off, Vp + gi);
        }
        cpa_commit();
    };
    load_kv(0, 0);

    float m0 = -1e30f, m1 = -1e30f, l0 = 0.f, l1 = 0.f;
    float oacc[8][4];
    #pragma unroll
    for (int i = 0; i < 8; i++)
        #pragma unroll
        for (int j = 0; j < 4; j++) oacc[i][j] = 0.f;

    uint32_t qaddr = sQ + ((qbase + (lane & 15))*KVW + ((lane >> 4) << 2))*4;
    uint32_t vfix  = ((lane & 15)*KVW + ((lane >> 4) << 2))*4;

    int ntile = Tk >> 6;
    for (int kt = 0; kt < ntile; kt++) {
        int buf = kt & 1;
        cpa_wait0();
        __syncthreads();
        if (kt + 1 < ntile) load_kv((kt + 1)*64, buf ^ 1);

        const uint32_t* Ksb = Ks + buf*64*KVW;
        float sacc[8][4];
        #pragma unroll
        for (int i = 0; i < 8; i++)
            #pragma unroll
            for (int j = 0; j < 4; j++) sacc[i][j] = 0.f;
        #pragma unroll
        for (int ks = 0; ks < 4; ks++) {
            uint32_t qf[4];
            ldsm4(qf, qaddr + ks*32);
            #pragma unroll
            for (int nt = 0; nt < 8; nt++) {
                uint32_t bf[2];
                const uint32_t* kp = &Ksb[(nt*8 + g)*KVW + ks*8 + tig];
                bf[0] = kp[0]; bf[1] = kp[4];
                mma_f16(sacc[nt], qf, bf);
            }
        }

        float mx0 = -1e30f, mx1 = -1e30f;
        #pragma unroll
        for (int nt = 0; nt < 8; nt++) {
            int2 mm = *(const int2*)&Msk[kt*64 + nt*8 + 2*tig];
            sacc[nt][0] = mm.x ? -1e30f : sacc[nt][0]*0.125f;
            sacc[nt][1] = mm.y ? -1e30f : sacc[nt][1]*0.125f;
            sacc[nt][2] = mm.x ? -1e30f : sacc[nt][2]*0.125f;
            sacc[nt][3] = mm.y ? -1e30f : sacc[nt][3]*0.125f;
            mx0 = fmaxf(mx0, fmaxf(sacc[nt][0], sacc[nt][1]));
            mx1 = fmaxf(mx1, fmaxf(sacc[nt][2], sacc[nt][3]));
        }
        mx0 = fmaxf(mx0, __shfl_xor_sync(0xffffffffu, mx0, 1));
        mx0 = fmaxf(mx0, __shfl_xor_sync(0xffffffffu, mx0, 2));
        mx1 = fmaxf(mx1, __shfl_xor_sync(0xffffffffu, mx1, 1));
        mx1 = fmaxf(mx1, __shfl_xor_sync(0xffffffffu, mx1, 2));
        float mn0 = fmaxf(m0, mx0), mn1 = fmaxf(m1, mx1);
        float scl0 = __expf(m0 - mn0), scl1 = __expf(m1 - mn1);
        m0 = mn0; m1 = mn1;

        uint32_t pf[4][4];
        float rs0 = 0.f, rs1 = 0.f;
        #pragma unroll
        for (int nt = 0; nt < 8; nt++) {
            float p0 = (sacc[nt][0] > -1e29f) ? __expf(sacc[nt][0] - mn0) : 0.f;
            float p1 = (sacc[nt][1] > -1e29f) ? __expf(sacc[nt][1] - mn0) : 0.f;
            float p2 = (sacc[nt][2] > -1e29f) ? __expf(sacc[nt][2] - mn1) : 0.f;
            float p3 = (sacc[nt][3] > -1e29f) ? __expf(sacc[nt][3] - mn1) : 0.f;
            rs0 += p0 + p1; rs1 += p2 + p3;
            pf[nt >> 1][0 + 2*(nt & 1)] = f2h2(p0, p1);
            pf[nt >> 1][1 + 2*(nt & 1)] = f2h2(p2, p3);
        }
        rs0 += __shfl_xor_sync(0xffffffffu, rs0, 1);
        rs0 += __shfl_xor_sync(0xffffffffu, rs0, 2);
        rs1 += __shfl_xor_sync(0xffffffffu, rs1, 1);
        rs1 += __shfl_xor_sync(0xffffffffu, rs1, 2);
        l0 = l0*scl0 + rs0;
        l1 = l1*scl1 + rs1;

        #pragma unroll
        for (int dt = 0; dt < 8; dt++) {
            oacc[dt][0] *= scl0; oacc[dt][1] *= scl0;
            oacc[dt][2] *= scl1; oacc[dt][3] *= scl1;
        }
        uint32_t vb = sV + (buf*64*KVW)*4;
        #pragma unroll
        for (int ks = 0; ks < 4; ks++) {
            uint32_t bv[4][4];
            #pragma unroll
            for (int j = 0; j < 4; j++)
                ldsm4t(bv[j], vb + (ks*16*KVW + j*8)*4 + vfix);
            #pragma unroll
            for (int dt = 0; dt < 8; dt++)
                mma_f16(oacc[dt], pf[ks], &bv[dt >> 1][(dt & 1)*2]);
        }
    }

    float inv0 = 1.f / l0, inv1 = 1.f / l1;
    int r0 = q0 + qbase + g;
    #pragma unroll
    for (int dt = 0; dt < 8; dt++) {
        int dd = dt*8 + 2*tig;
        *(uint32_t*)&Y[((size_t) r0     *B_ + b)*C_ + hoff + dd] =
            f2h2(oacc[dt][0]*inv0, oacc[dt][1]*inv0);
        *(uint32_t*)&Y[((size_t)(r0 + 8)*B_ + b)*C_ + hoff + dd] =
            f2h2(oacc[dt][2]*inv1, oacc[dt][3]*inv1);
    }
}

// ---------------- launch -----------------------------------------------------
extern "C" void kernel_launch(void* const* d_in, const int* in_sizes, int n_in,
                              void* d_out, int out_size) {
    const float* x     = (const float*)d_in[0];
    const float* c     = (const float*)d_in[1];
    const int*   pmask = (const int*)  d_in[2];
    const float* audio = (const float*)d_in[3];
    const int*   amask = (const int*)  d_in[4];
    const float* w_ada = (const float*)d_in[5];
    const float* b_ada = (const float*)d_in[6];
    const float* wq = (const float*)d_in[7];   const float* bq = (const float*)d_in[8];
    const float* wk = (const float*)d_in[9];   const float* bk = (const float*)d_in[10];
    const float* wv = (const float*)d_in[11];  const float* bv = (const float*)d_in[12];
    const float* wo = (const float*)d_in[13];  const float* bo = (const float*)d_in[14];
    const float* cwq = (const float*)d_in[15]; const float* cbq = (const float*)d_in[16];
    const float* cwk = (const float*)d_in[17]; const float* cbk = (const float*)d_in[18];
    const float* cwv = (const float*)d_in[19]; const float* cbv = (const float*)d_in[20];
    const float* cwo = (const float*)d_in[21]; const float* cbo = (const float*)d_in[22];
    const float* w1 = (const float*)d_in[23];  const float* b1 = (const float*)d_in[24];
    const float* w2 = (const float*)d_in[25];  const float* b2 = (const float*)d_in[26];
    float* out = (float*)d_out;

    float  *modp;
    __half *whp, *ahp, *lnp, *qkvp, *qkv2p, *yp, *hp;
    cudaGetSymbolAddress((void**)&modp,  g_mod);
    cudaGetSymbolAddress((void**)&whp,   g_wh);
    cudaGetSymbolAddress((void**)&ahp,   g_ah);
    cudaGetSymbolAddress((void**)&lnp,   g_lnh);
    cudaGetSymbolAddress((void**)&qkvp,  g_qkv);
    cudaGetSymbolAddress((void**)&qkv2p, g_qkv2);
    cudaGetSymbolAddress((void**)&yp,    g_yh);
    cudaGetSymbolAddress((void**)&hp,    g_hh);

    cudaFuncSetAttribute(fattn_k, cudaFuncAttributeMaxDynamicSharedMemorySize, ATT_SMEM);

    dim3 gQKV(24, 64);
    dim3 gKV(16, 64);
    dim3 gQ(8, 64);
    dim3 gC(8, 64);
    dim3 gM(32, 64);
    dim3 gA(T_/128, H_, B_);

    // ---- fork side stream: weight/audio converts + cross K/V projection ----
    cudaEventRecord(g_evFork, 0);
    cudaStreamWaitEvent(g_s1, g_evFork, 0);
    f2h8_k<<<dim3((C_*C_)/2048, 8), 256, 0, g_s1>>>(wq, wk, wv, wo, cwq, cwk, cwv, cwo, whp);
    f2hm_k<<<dim3(2048, 4), 256, 0, g_s1>>>(w1, w2, audio, whp, ahp);
    cudaEventRecord(g_evConv, g_s1);
    hgemm_kv_k<<<gKV, 128, 0, g_s1>>>(ahp, whp, cbk, cbv, qkv2p, WOFF_CQ, C_);
    cudaEventRecord(g_evKV, g_s1);

    // ---- main stream prologue (parallel with converts) ----
    mod_k<<<SIXC/256, 256>>>(c, w_ada, b_ada, modp);
    ln_mod_k<1><<<R_, 256>>>(x, modp, 0, C_, lnp, out);   // residual init + LN

    // ---- self attention (needs converted weights) ----
    cudaStreamWaitEvent(0, g_evConv, 0);
    hgemm_qkv_k<<<gQKV, 128>>>(lnp, whp, bq, bk, bv, qkvp, WOFF_Q, C_);
    fattn_k<<<gA, 256, ATT_SMEM>>>(qkvp, pmask, yp, T_);
    hgemm_k<2, float><<<gC, 128>>>(yp, whp + WOFF_O, bo, out, modp + 2*C_, C_, C_);

    // ---- cross attention (K/V computed on side stream) ----
    ln_mod_k<0><<<R_, 256>>>(out, modp, 0, C_, lnp, nullptr);
    hgemm_q_k<<<gQ, 128>>>(lnp, whp, cbq, qkv2p, WOFF_CQ, C_);
    cudaStreamWaitEvent(0, g_evKV, 0);
    fattn_k<<<gA, 256, ATT_SMEM>>>(qkv2p, amask, yp, TA_);
    hgemm_k<2, float><<<gC, 128>>>(yp, whp + WOFF_CO, cbo, out, modp + 2*C_, C_, C_);

    // ---- MLP ----
    ln_mod_k<0><<<R_, 256>>>(out, modp, 3*C_, 4*C_, lnp, nullptr);
    hgemm_k<1, __half><<<gM, 128>>>(lnp, whp + WOFF_W1, b1, hp, nullptr, C_, M_);
    hgemm_k<2, float><<<gC, 128>>>(hp, whp + WOFF_W2, b2, out, modp + 5*C_, M_, C_);
}

// round 13
// speedup vs baseline: 1.5622x; 1.0591x over previous
#include <cuda_runtime.h>
#include <cuda_fp16.h>
#include <math.h>
#include <stdint.h>

#define T_  1024
#define B_  8
#define C_  1024
#define H_  16
#define D_  64
#define M_  4096
#define TA_ 1024
#define R_  (T_*B_)
#define SIXC (6*C_)
#define NSPLIT 8

// ---------------- scratch (device globals) -----------------------------------
__device__ float  g_mod[B_*SIXC];
__device__ float  g_modpart[NSPLIT*B_*SIXC];
__device__ __half g_wh [16*1024*1024];     // packed fp16 weights [K,N]
__device__ __half g_ah [(size_t)R_*C_];    // audio fp16
__device__ __half g_lnh[(size_t)R_*C_];    // ln+modulate fp16
__device__ __half g_qkv [(size_t)R_*3*C_]; // self q|k|v fp16, row stride 3C
__device__ __half g_qkv2[(size_t)R_*3*C_]; // cross q|k|v fp16, row stride 3C
__device__ __half g_yh [(size_t)R_*C_];    // attention out fp16
__device__ __half g_hh [(size_t)R_*M_];    // mlp hidden fp16

#define WOFF_Q   (0)
#define WOFF_O   (3*1024*1024)
#define WOFF_CQ  (4*1024*1024)
#define WOFF_CO  (7*1024*1024)
#define WOFF_W1  (8*1024*1024)
#define WOFF_W2  (12*1024*1024)

// ---------------- side stream + events (created once at load) ----------------
static cudaStream_t g_s1;
static cudaEvent_t  g_evFork, g_evConv, g_evKV;
struct _StreamInit {
    _StreamInit() {
        cudaStreamCreateWithFlags(&g_s1, cudaStreamNonBlocking);
        cudaEventCreateWithFlags(&g_evFork, cudaEventDisableTiming);
        cudaEventCreateWithFlags(&g_evConv, cudaEventDisableTiming);
        cudaEventCreateWithFlags(&g_evKV,   cudaEventDisableTiming);
    }
};
static _StreamInit _stream_init;

// ---------------- helpers ----------------------------------------------------
__device__ __forceinline__ float gelu_tanh(float x) {
    float x3 = x*x*x;
    return 0.5f*x*(1.f + tanhf(0.7978845608028654f*(x + 0.044715f*x3)));
}
__device__ __forceinline__ uint32_t f2h2(float lo, float hi) {
    __half2 h = __floats2half2_rn(lo, hi);
    return *reinterpret_cast<uint32_t*>(&h);
}
__device__ __forceinline__ void mma_f16(float* d, const uint32_t* a, const uint32_t* b) {
    asm volatile(
        "mma.sync.aligned.m16n8k16.row.col.f32.f16.f16.f32 "
        "{%0,%1,%2,%3}, {%4,%5,%6,%7}, {%8,%9}, {%0,%1,%2,%3};\n"
        : "+f"(d[0]), "+f"(d[1]), "+f"(d[2]), "+f"(d[3])
        : "r"(a[0]), "r"(a[1]), "r"(a[2]), "r"(a[3]), "r"(b[0]), "r"(b[1]));
}
__device__ __forceinline__ void ldsm4(uint32_t* r, uint32_t addr) {
    asm volatile("ldmatrix.sync.aligned.m8n8.x4.shared.b16 {%0,%1,%2,%3}, [%4];"
        : "=r"(r[0]), "=r"(r[1]), "=r"(r[2]), "=r"(r[3]) : "r"(addr));
}
__device__ __forceinline__ void ldsm4t(uint32_t* r, uint32_t addr) {
    asm volatile("ldmatrix.sync.aligned.m8n8.x4.trans.shared.b16 {%0,%1,%2,%3}, [%4];"
        : "=r"(r[0]), "=r"(r[1]), "=r"(r[2]), "=r"(r[3]) : "r"(addr));
}
__device__ __forceinline__ void cpa16(uint32_t dst, const void* src) {
    asm volatile("cp.async.ca.shared.global [%0], [%1], 16;\n" :: "r"(dst), "l"(src));
}
__device__ __forceinline__ void cpa_commit() { asm volatile("cp.async.commit_group;\n"); }
__device__ __forceinline__ void cpa_wait1()  { asm volatile("cp.async.wait_group 1;\n"); }
__device__ __forceinline__ void cpa_wait0()  { asm volatile("cp.async.wait_group 0;\n"); }

// ---------------- small utility kernels --------------------------------------
__global__ void f2h8_k(const float* __restrict__ p0, const float* __restrict__ p1,
                       const float* __restrict__ p2, const float* __restrict__ p3,
                       const float* __restrict__ p4, const float* __restrict__ p5,
                       const float* __restrict__ p6, const float* __restrict__ p7,
                       __half* __restrict__ out) {
    const float* src;
    switch (blockIdx.y) {
        case 0: src = p0; break; case 1: src = p1; break;
        case 2: src = p2; break; case 3: src = p3; break;
        case 4: src = p4; break; case 5: src = p5; break;
        case 6: src = p6; break; default: src = p7; break;
    }
    int i = (blockIdx.x*256 + threadIdx.x)*8;
    float4 a = *(const float4*)&src[i];
    float4 b = *(const float4*)&src[i+4];
    *(uint4*)&out[(size_t)blockIdx.y*(C_*C_) + i] =
        make_uint4(f2h2(a.x,a.y), f2h2(a.z,a.w), f2h2(b.x,b.y), f2h2(b.z,b.w));
}
__global__ void f2hm_k(const float* __restrict__ w1, const float* __restrict__ w2,
                       const float* __restrict__ audio,
                       __half* __restrict__ wh, __half* __restrict__ ah) {
    const float* src; __half* dst;
    switch (blockIdx.y) {
        case 0: src = w1; dst = wh + WOFF_W1; break;
        case 1: src = w2; dst = wh + WOFF_W2; break;
        case 2: src = audio; dst = ah; break;
        default: src = audio + 4*1024*1024; dst = ah + 4*1024*1024; break;
    }
    int i = (blockIdx.x*256 + threadIdx.x)*8;
    float4 a = *(const float4*)&src[i];
    float4 b = *(const float4*)&src[i+4];
    *(uint4*)&dst[i] = make_uint4(f2h2(a.x,a.y), f2h2(a.z,a.w),
                                  f2h2(b.x,b.y), f2h2(b.z,b.w));
}

// ---------------- adaLN modulation: split-K, deterministic 2-stage -----------
// stage 1: grid (SIXC/256, NSPLIT); split s covers k in [128s, 128s+128)
__global__ void mod1_k(const float* __restrict__ c, const float* __restrict__ w,
                       float* __restrict__ part) {
    __shared__ float sc[B_][128];
    int tid = threadIdx.x;
    int s   = blockIdx.y;
    int k0  = s*128;
    for (int i = tid; i < B_*128; i += 256) {
        int b = i >> 7, k = i & 127;
        float v = c[b*C_ + k0 + k];
        sc[b][k] = v / (1.f + __expf(-v));
    }
    __syncthreads();
    int col = blockIdx.x*256 + tid;
    float acc[B_];
    #pragma unroll
    for (int b = 0; b < B_; b++) acc[b] = 0.f;
    for (int k = 0; k < 128; k++) {
        float wv = w[(size_t)(k0 + k)*SIXC + col];
        #pragma unroll
        for (int b = 0; b < B_; b++) acc[b] += sc[b][k]*wv;
    }
    float* dst = part + (size_t)s*B_*SIXC;
    #pragma unroll
    for (int b = 0; b < B_; b++) dst[b*SIXC + col] = acc[b];
}
// stage 2: fixed-order reduction + bias
__global__ void mod2_k(const float* __restrict__ part, const float* __restrict__ bias,
                       float* __restrict__ mod) {
    int col = blockIdx.x*256 + threadIdx.x;
    float bb = bias[col];
    #pragma unroll
    for (int b = 0; b < B_; b++) {
        float s = 0.f;
        #pragma unroll
        for (int p = 0; p < NSPLIT; p++)
            s += part[(size_t)p*B_*SIXC + b*SIXC + col];
        mod[b*SIXC + col] = s + bb;
    }
}

// ---------------- LN (no affine) + modulate -> fp16 --------------------------
template<int COPY>
__global__ void ln_mod_k(const float* __restrict__ x, const float* __restrict__ mod,
                         int shiftOff, int scaleOff, __half* __restrict__ out,
                         float* __restrict__ res) {
    int row = blockIdx.x;
    int b   = row & (B_-1);
    int tid = threadIdx.x;
    const float* xr = x + (size_t)row*C_;
    float4 v = *(const float4*)&xr[tid*4];
    if (COPY) *(float4*)&res[(size_t)row*C_ + tid*4] = v;
    float s  = v.x + v.y + v.z + v.w;
    float s2 = v.x*v.x + v.y*v.y + v.z*v.z + v.w*v.w;
    #pragma unroll
    for (int o = 16; o; o >>= 1) {
        s  += __shfl_xor_sync(0xffffffffu, s,  o);
        s2 += __shfl_xor_sync(0xffffffffu, s2, o);
    }
    __shared__ float red[2][8];
    int w = tid >> 5, ln = tid & 31;
    if (ln == 0) { red[0][w] = s; red[1][w] = s2; }
    __syncthreads();
    s = 0.f; s2 = 0.f;
    #pragma unroll
    for (int i = 0; i < 8; i++) { s += red[0][i]; s2 += red[1][i]; }
    float mu   = s * (1.f/C_);
    float var  = s2 * (1.f/C_) - mu*mu;
    float rstd = rsqrtf(var + 1e-6f);
    const float* sh = mod + b*SIXC + shiftOff + tid*4;
    const float* sc = mod + b*SIXC + scaleOff + tid*4;
    float4 shv = *(const float4*)sh;
    float4 scv = *(const float4*)sc;
    float m0 = (v.x-mu)*rstd*(1.f+scv.x) + shv.x;
    float m1 = (v.y-mu)*rstd*(1.f+scv.y) + shv.y;
    float m2 = (v.z-mu)*rstd*(1.f+scv.z) + shv.z;
    float m3 = (v.w-mu)*rstd*(1.f+scv.w) + shv.w;
    *(uint2*)&out[(size_t)row*C_ + tid*4] = make_uint2(f2h2(m0,m1), f2h2(m2,m3));
}

// ---------------- fp16 GEMM 128x128, BK=32, 128 thr, warp tile 64x64 ---------
#define SAW 12
#define SBW 68
#define ABUF (2*128*SAW)
#define BBUF (2*16*SBW)

template<int EPI, typename OT>
__device__ __forceinline__ void gemm_body(
    uint32_t* AsS, uint32_t* BsS,
    const __half* __restrict__ A, const __half* __restrict__ W,
    const float* __restrict__ bias, OT* __restrict__ out,
    const float* __restrict__ gate,
    int K, int N, int row0, int col0, size_t ostride, int ocol0)
{
    int tid  = threadIdx.x;
    int lane = tid & 31, wid = tid >> 5;
    int g    = lane >> 2, tig = lane & 3;
    int wm   = wid >> 1, wn = wid & 1;

    uint32_t sA0 = (uint32_t)__cvta_generic_to_shared(AsS);
    uint32_t sB0 = (uint32_t)__cvta_generic_to_shared(BsS);

    float acc[4][8][4];
    #pragma unroll
    for (int i = 0; i < 4; i++)
        #pragma unroll
        for (int j = 0; j < 8; j++)
            #pragma unroll
            for (int q = 0; q < 4; q++) acc[i][j][q] = 0.f;

    auto load_chunk = [&](int k0, int bf) {
        #pragma unroll
        for (int p = 0; p < 4; p++) {
            int idx = tid + p*128;
            int row = idx >> 2, q = idx & 3, ks = q >> 1, hs = q & 1;
            const __half* src = A + (size_t)(row0 + row)*K + k0 + ks*16 + hs*8;
            uint32_t dst = sA0 + (bf*ABUF + ks*128*SAW + row*SAW + hs*4)*4;
            cpa16(dst, src);
        }
        #pragma unroll
        for (int p = 0; p < 4; p++) {
            int idx = tid + p*128;
            int kr = idx >> 4, nc = idx & 15;
            const __half* src = W + (size_t)(k0 + kr)*N + col0 + nc*8;
            uint32_t dst = sB0 + (bf*BBUF + (kr>>4)*16*SBW + (kr&15)*SBW + nc*4)*4;
            cpa16(dst, src);
        }
        cpa_commit();
    };

    load_chunk(0, 0);

    int buf = 0;
    int nchunk = K >> 5;
    for (int ch = 0; ch < nchunk; ch++) {
        bool more = (ch + 1 < nchunk);
        if (more) { load_chunk((ch + 1)*32, buf ^ 1); cpa_wait1(); }
        else      { cpa_wait0(); }
        __syncthreads();

        #pragma unroll
        for (int ks = 0; ks < 2; ks++) {
            uint32_t sA = sA0 + (buf*ABUF + ks*128*SAW)*4;
            uint32_t sB = sB0 + (buf*BBUF + ks*16*SBW)*4;
            uint32_t af[4][4];
            #pragma unroll
            for (int mt = 0; mt < 4; mt++) {
                uint32_t addr = sA + ((wm*64 + mt*16 + (lane & 15))*SAW + ((lane >> 4) << 2))*4;
                ldsm4(af[mt], addr);
            }
            uint32_t bq[4][4];
            #pragma unroll
            for (int hf = 0; hf < 4; hf++) {
                uint32_t addr = sB + ((lane & 15)*SBW + (wn*32 + hf*8) + ((lane >> 4) << 2))*4;
                ldsm4t(bq[hf], addr);
            }
            #pragma unroll
            for (int mt = 0; mt < 4; mt++)
                #pragma unroll
                for (int nt = 0; nt < 8; nt++)
                    mma_f16(acc[mt][nt], af[mt], &bq[nt >> 1][(nt & 1)*2]);
        }
        __syncthreads();
        buf ^= 1;
    }

    #pragma unroll
    for (int mt = 0; mt < 4; mt++) {
        int rbase = row0 + wm*64 + mt*16 + g;
        #pragma unroll
        for (int half = 0; half < 2; half++) {
            int rr = rbase + 8*half;
            int bb = rr & (B_-1);
            OT* orow = out + (size_t)rr*ostride + ocol0;
            #pragma unroll
            for (int nt = 0; nt < 8; nt++) {
                int cl = col0 + wn*64 + nt*8 + 2*tig;
                float v0 = acc[mt][nt][2*half + 0] + bias[cl];
                float v1 = acc[mt][nt][2*half + 1] + bias[cl+1];
                if (EPI == 2) {
                    float* fr = (float*)orow;
                    fr[cl]   += gate[bb*SIXC + cl  ]*v0;
                    fr[cl+1] += gate[bb*SIXC + cl+1]*v1;
                } else if (EPI == 1) {
                    *(uint32_t*)&orow[cl] = f2h2(gelu_tanh(v0), gelu_tanh(v1));
                } else {
                    *(uint32_t*)&orow[cl] = f2h2(v0, v1);
                }
            }
        }
    }
}

template<int EPI, typename OT>
__global__ void __launch_bounds__(128, 2)
hgemm_k(const __half* __restrict__ A, const __half* __restrict__ W,
        const float* __restrict__ bias, OT* __restrict__ out,
        const float* __restrict__ gate, int K, int N) {
    __shared__ __align__(16) uint32_t As[2*ABUF];
    __shared__ __align__(16) uint32_t Bs[2*BBUF];
    gemm_body<EPI, OT>(As, Bs, A, W, bias, out, gate, K, N,
                       blockIdx.y*128, blockIdx.x*128, N, 0);
}

__global__ void __launch_bounds__(128, 2)
hgemm_qkv_k(const __half* __restrict__ A, const __half* __restrict__ Wbase,
            const float* __restrict__ b0, const float* __restrict__ b1,
            const float* __restrict__ b2,
            __half* __restrict__ out, int woff0, int K) {
    __shared__ __align__(16) uint32_t As[2*ABUF];
    __shared__ __align__(16) uint32_t Bs[2*BBUF];
    int sel = blockIdx.x >> 3;
    int nb  = blockIdx.x & 7;
    const __half* W    = Wbase + woff0 + sel*(C_*C_);
    const float* bias  = (sel == 0) ? b0 : (sel == 1) ? b1 : b2;
    gemm_body<0, __half>(As, Bs, A, W, bias, out, nullptr, K, C_,
                         blockIdx.y*128, nb*128, 3*C_, sel*C_);
}
__global__ void __launch_bounds__(128, 2)
hgemm_kv_k(const __half* __restrict__ A, const __half* __restrict__ Wbase,
           const float* __restrict__ b1, const float* __restrict__ b2,
           __half* __restrict__ out, int woff0, int K) {
    __shared__ __align__(16) uint32_t As[2*ABUF];
    __shared__ __align__(16) uint32_t Bs[2*BBUF];
    int sel = 1 + (blockIdx.x >> 3);
    int nb  = blockIdx.x & 7;
    const __half* W    = Wbase + woff0 + sel*(C_*C_);
    const float* bias  = (sel == 1) ? b1 : b2;
    gemm_body<0, __half>(As, Bs, A, W, bias, out, nullptr, K, C_,
                         blockIdx.y*128, nb*128, 3*C_, sel*C_);
}
__global__ void __launch_bounds__(128, 2)
hgemm_q_k(const __half* __restrict__ A, const __half* __restrict__ Wbase,
          const float* __restrict__ b0, __half* __restrict__ out,
          int woff0, int K) {
    __shared__ __align__(16) uint32_t As[2*ABUF];
    __shared__ __align__(16) uint32_t Bs[2*BBUF];
    gemm_body<0, __half>(As, Bs, A, Wbase + woff0, b0, out, nullptr, K, C_,
                         blockIdx.y*128, blockIdx.x*128, 3*C_, 0);
}

// ---------------- register-resident fp16 flash attention ---------------------
#define KVW 36
#define ATT_SMEM ((128*KVW + 4*64*KVW)*4 + 1024*4)
__global__ void __launch_bounds__(256, 2)
fattn_k(const __half* __restrict__ QKV, const int* __restrict__ mask,
        __half* __restrict__ Y, int Tk) {
    extern __shared__ uint32_t smu[];
    uint32_t* Qs = smu;
    uint32_t* Ks = Qs + 128*KVW;
    uint32_t* Vs = Ks + 2*64*KVW;
    int*      Msk = (int*)(Vs + 2*64*KVW);

    int tid  = threadIdx.x;
    int lane = tid & 31, wid = tid >> 5;
    int g    = lane >> 2, tig = lane & 3;
    int qbase = wid*16;
    int q0 = blockIdx.x*128, h = blockIdx.y, b = blockIdx.z;
    size_t hoff = (size_t)h*D_;
    const int RS = 3*C_;
    const __half* Kp = QKV + C_;
    const __half* Vp = QKV + 2*C_;

    uint32_t sQ = (uint32_t)__cvta_generic_to_shared(Qs);
    uint32_t sK = (uint32_t)__cvta_generic_to_shared(Ks);
    uint32_t sV = (uint32_t)__cvta_generic_to_shared(Vs);

    for (int i = tid; i < (Tk >> 2); i += 256)
        *(int4*)&Msk[i*4] = *(const int4*)&mask[(size_t)b*Tk + i*4];

    #pragma unroll
    for (int p = 0; p < 4; p++) {
        int idx = tid + p*256;
        int r = idx >> 3, c8 = idx & 7;
        *(uint4*)&Qs[r*KVW + c8*4] =
            *(const uint4*)&QKV[((size_t)(q0+r)*B_ + b)*RS + hoff + c8*8];
    }

    auto load_kv = [&](int k0, int bf) {
        #pragma unroll
        for (int p = 0; p < 2; p++) {
            int idx = tid + p*256;
            int r = idx >> 3, c8 = idx & 7;
            size_t gi = ((size_t)(k0+r)*B_ + b)*RS + hoff + c8*8;
            uint32_t off = (bf*64*KVW + r*KVW + c8*4)*4;
            cpa16(sK + off, Kp + gi);
            cpa16(sV + off, Vp + gi);
        }
        cpa_commit();
    };
    load_kv(0, 0);

    float m0 = -1e30f, m1 = -1e30f, l0 = 0.f, l1 = 0.f;
    float oacc[8][4];
    #pragma unroll
    for (int i = 0; i < 8; i++)
        #pragma unroll
        for (int j = 0; j < 4; j++) oacc[i][j] = 0.f;

    uint32_t qaddr = sQ + ((qbase + (lane & 15))*KVW + ((lane >> 4) << 2))*4;
    uint32_t vfix  = ((lane & 15)*KVW + ((lane >> 4) << 2))*4;

    int ntile = Tk >> 6;
    for (int kt = 0; kt < ntile; kt++) {
        int buf = kt & 1;
        cpa_wait0();
        __syncthreads();
        if (kt + 1 < ntile) load_kv((kt + 1)*64, buf ^ 1);

        const uint32_t* Ksb = Ks + buf*64*KVW;
        float sacc[8][4];
        #pragma unroll
        for (int i = 0; i < 8; i++)
            #pragma unroll
            for (int j = 0; j < 4; j++) sacc[i][j] = 0.f;
        #pragma unroll
        for (int ks = 0; ks < 4; ks++) {
            uint32_t qf[4];
            ldsm4(qf, qaddr + ks*32);
            #pragma unroll
            for (int nt = 0; nt < 8; nt++) {
                uint32_t bf[2];
                const uint32_t* kp = &Ksb[(nt*8 + g)*KVW + ks*8 + tig];
                bf[0] = kp[0]; bf[1] = kp[4];
                mma_f16(sacc[nt], qf, bf);
            }
        }

        float mx0 = -1e30f, mx1 = -1e30f;
        #pragma unroll
        for (int nt = 0; nt < 8; nt++) {
            int2 mm = *(const int2*)&Msk[kt*64 + nt*8 + 2*tig];
            sacc[nt][0] = mm.x ? -1e30f : sacc[nt][0]*0.125f;
            sacc[nt][1] = mm.y ? -1e30f : sacc[nt][1]*0.125f;
            sacc[nt][2] = mm.x ? -1e30f : sacc[nt][2]*0.125f;
            sacc[nt][3] = mm.y ? -1e30f : sacc[nt][3]*0.125f;
            mx0 = fmaxf(mx0, fmaxf(sacc[nt][0], sacc[nt][1]));
            mx1 = fmaxf(mx1, fmaxf(sacc[nt][2], sacc[nt][3]));
        }
        mx0 = fmaxf(mx0, __shfl_xor_sync(0xffffffffu, mx0, 1));
        mx0 = fmaxf(mx0, __shfl_xor_sync(0xffffffffu, mx0, 2));
        mx1 = fmaxf(mx1, __shfl_xor_sync(0xffffffffu, mx1, 1));
        mx1 = fmaxf(mx1, __shfl_xor_sync(0xffffffffu, mx1, 2));
        float mn0 = fmaxf(m0, mx0), mn1 = fmaxf(m1, mx1);
        float scl0 = __expf(m0 - mn0), scl1 = __expf(m1 - mn1);
        m0 = mn0; m1 = mn1;

        uint32_t pf[4][4];
        float rs0 = 0.f, rs1 = 0.f;
        #pragma unroll
        for (int nt = 0; nt < 8; nt++) {
            float p0 = (sacc[nt][0] > -1e29f) ? __expf(sacc[nt][0] - mn0) : 0.f;
            float p1 = (sacc[nt][1] > -1e29f) ? __expf(sacc[nt][1] - mn0) : 0.f;
            float p2 = (sacc[nt][2] > -1e29f) ? __expf(sacc[nt][2] - mn1) : 0.f;
            float p3 = (sacc[nt][3] > -1e29f) ? __expf(sacc[nt][3] - mn1) : 0.f;
            rs0 += p0 + p1; rs1 += p2 + p3;
            pf[nt >> 1][0 + 2*(nt & 1)] = f2h2(p0, p1);
            pf[nt >> 1][1 + 2*(nt & 1)] = f2h2(p2, p3);
        }
        rs0 += __shfl_xor_sync(0xffffffffu, rs0, 1);
        rs0 += __shfl_xor_sync(0xffffffffu, rs0, 2);
        rs1 += __shfl_xor_sync(0xffffffffu, rs1, 1);
        rs1 += __shfl_xor_sync(0xffffffffu, rs1, 2);
        l0 = l0*scl0 + rs0;
        l1 = l1*scl1 + rs1;

        #pragma unroll
        for (int dt = 0; dt < 8; dt++) {
            oacc[dt][0] *= scl0; oacc[dt][1] *= scl0;
            oacc[dt][2] *= scl1; oacc[dt][3] *= scl1;
        }
        uint32_t vb = sV + (buf*64*KVW)*4;
        #pragma unroll
        for (int ks = 0; ks < 4; ks++) {
            uint32_t bv[4][4];
            #pragma unroll
            for (int j = 0; j < 4; j++)
                ldsm4t(bv[j], vb + (ks*16*KVW + j*8)*4 + vfix);
            #pragma unroll
            for (int dt = 0; dt < 8; dt++)
                mma_f16(oacc[dt], pf[ks], &bv[dt >> 1][(dt & 1)*2]);
        }
    }

    float inv0 = 1.f / l0, inv1 = 1.f / l1;
    int r0 = q0 + qbase + g;
    #pragma unroll
    for (int dt = 0; dt < 8; dt++) {
        int dd = dt*8 + 2*tig;
        *(uint32_t*)&Y[((size_t) r0     *B_ + b)*C_ + hoff + dd] =
            f2h2(oacc[dt][0]*inv0, oacc[dt][1]*inv0);
        *(uint32_t*)&Y[((size_t)(r0 + 8)*B_ + b)*C_ + hoff + dd] =
            f2h2(oacc[dt][2]*inv1, oacc[dt][3]*inv1);
    }
}

// ---------------- launch -----------------------------------------------------
extern "C" void kernel_launch(void* const* d_in, const int* in_sizes, int n_in,
                              void* d_out, int out_size) {
    const float* x     = (const float*)d_in[0];
    const float* c     = (const float*)d_in[1];
    const int*   pmask = (const int*)  d_in[2];
    const float* audio = (const float*)d_in[3];
    const int*   amask = (const int*)  d_in[4];
    const float* w_ada = (const float*)d_in[5];
    const float* b_ada = (const float*)d_in[6];
    const float* wq = (const float*)d_in[7];   const float* bq = (const float*)d_in[8];
    const float* wk = (const float*)d_in[9];   const float* bk = (const float*)d_in[10];
    const float* wv = (const float*)d_in[11];  const float* bv = (const float*)d_in[12];
    const float* wo = (const float*)d_in[13];  const float* bo = (const float*)d_in[14];
    const float* cwq = (const float*)d_in[15]; const float* cbq = (const float*)d_in[16];
    const float* cwk = (const float*)d_in[17]; const float* cbk = (const float*)d_in[18];
    const float* cwv = (const float*)d_in[19]; const float* cbv = (const float*)d_in[20];
    const float* cwo = (const float*)d_in[21]; const float* cbo = (const float*)d_in[22];
    const float* w1 = (const float*)d_in[23];  const float* b1 = (const float*)d_in[24];
    const float* w2 = (const float*)d_in[25];  const float* b2 = (const float*)d_in[26];
    float* out = (float*)d_out;

    float  *modp, *partp;
    __half *whp, *ahp, *lnp, *qkvp, *qkv2p, *yp, *hp;
    cudaGetSymbolAddress((void**)&modp,  g_mod);
    cudaGetSymbolAddress((void**)&partp, g_modpart);
    cudaGetSymbolAddress((void**)&whp,   g_wh);
    cudaGetSymbolAddress((void**)&ahp,   g_ah);
    cudaGetSymbolAddress((void**)&lnp,   g_lnh);
    cudaGetSymbolAddress((void**)&qkvp,  g_qkv);
    cudaGetSymbolAddress((void**)&qkv2p, g_qkv2);
    cudaGetSymbolAddress((void**)&yp,    g_yh);
    cudaGetSymbolAddress((void**)&hp,    g_hh);

    cudaFuncSetAttribute(fattn_k, cudaFuncAttributeMaxDynamicSharedMemorySize, ATT_SMEM);

    dim3 gQKV(24, 64);
    dim3 gKV(16, 64);
    dim3 gQ(8, 64);
    dim3 gC(8, 64);
    dim3 gM(32, 64);
    dim3 gA(T_/128, H_, B_);

    // ---- fork side stream: weight/audio converts + cross K/V projection ----
    cudaEventRecord(g_evFork, 0);
    cudaStreamWaitEvent(g_s1, g_evFork, 0);
    f2h8_k<<<dim3((C_*C_)/2048, 8), 256, 0, g_s1>>>(wq, wk, wv, wo, cwq, cwk, cwv, cwo, whp);
    f2hm_k<<<dim3(2048, 4), 256, 0, g_s1>>>(w1, w2, audio, whp, ahp);
    cudaEventRecord(g_evConv, g_s1);
    hgemm_kv_k<<<gKV, 128, 0, g_s1>>>(ahp, whp, cbk, cbv, qkv2p, WOFF_CQ, C_);
    cudaEventRecord(g_evKV, g_s1);

    // ---- main stream prologue (parallel with converts) ----
    mod1_k<<<dim3(SIXC/256, NSPLIT), 256>>>(c, w_ada, partp);
    mod2_k<<<SIXC/256, 256>>>(partp, b_ada, modp);
    ln_mod_k<1><<<R_, 256>>>(x, modp, 0, C_, lnp, out);   // residual init + LN

    // ---- self attention (needs converted weights) ----
    cudaStreamWaitEvent(0, g_evConv, 0);
    hgemm_qkv_k<<<gQKV, 128>>>(lnp, whp, bq, bk, bv, qkvp, WOFF_Q, C_);
    fattn_k<<<gA, 256, ATT_SMEM>>>(qkvp, pmask, yp, T_);
    hgemm_k<2, float><<<gC, 128>>>(yp, whp + WOFF_O, bo, out, modp + 2*C_, C_, C_);

    // ---- cross attention (K/V computed on side stream) ----
    ln_mod_k<0><<<R_, 256>>>(out, modp, 0, C_, lnp, nullptr);
    hgemm_q_k<<<gQ, 128>>>(lnp, whp, cbq, qkv2p, WOFF_CQ, C_);
    cudaStreamWaitEvent(0, g_evKV, 0);
    fattn_k<<<gA, 256, ATT_SMEM>>>(qkv2p, amask, yp, TA_);
    hgemm_k<2, float><<<gC, 128>>>(yp, whp + WOFF_CO, cbo, out, modp + 2*C_, C_, C_);

    // ---- MLP ----
    ln_mod_k<0><<<R_, 256>>>(out, modp, 3*C_, 4*C_, lnp, nullptr);
    hgemm_k<1, __half><<<gM, 128>>>(lnp, whp + WOFF_W1, b1, hp, nullptr, C_, M_);
    hgemm_k<2, float><<<gC, 128>>>(hp, whp + WOFF_W2, b2, out, modp + 5*C_, M_, C_);
}

// round 14
// speedup vs baseline: 1.5813x; 1.0123x over previous
#include <cuda_runtime.h>
#include <cuda_fp16.h>
#include <math.h>
#include <stdint.h>

#define T_  1024
#define B_  8
#define C_  1024
#define H_  16
#define D_  64
#define M_  4096
#define TA_ 1024
#define R_  (T_*B_)
#define SIXC (6*C_)
#define NSPLIT 32

// ---------------- scratch (device globals) -----------------------------------
__device__ float  g_mod[B_*SIXC];
__device__ float  g_modpart[NSPLIT*B_*SIXC];
__device__ __half g_wh [16*1024*1024];     // packed fp16 weights [K,N]
__device__ __half g_ah [(size_t)R_*C_];    // audio fp16
__device__ __half g_lnh[(size_t)R_*C_];    // ln+modulate fp16
__device__ __half g_qkv [(size_t)R_*3*C_]; // self q|k|v fp16, row stride 3C
__device__ __half g_qkv2[(size_t)R_*3*C_]; // cross q|k|v fp16, row stride 3C
__device__ __half g_yh [(size_t)R_*C_];    // attention out fp16
__device__ __half g_hh [(size_t)R_*M_];    // mlp hidden fp16

#define WOFF_Q   (0)
#define WOFF_O   (3*1024*1024)
#define WOFF_CQ  (4*1024*1024)
#define WOFF_CO  (7*1024*1024)
#define WOFF_W1  (8*1024*1024)
#define WOFF_W2  (12*1024*1024)

// ---------------- side stream + events (created once at load) ----------------
static cudaStream_t g_s1;
static cudaEvent_t  g_evFork, g_evConv, g_evKV;
struct _StreamInit {
    _StreamInit() {
        cudaStreamCreateWithFlags(&g_s1, cudaStreamNonBlocking);
        cudaEventCreateWithFlags(&g_evFork, cudaEventDisableTiming);
        cudaEventCreateWithFlags(&g_evConv, cudaEventDisableTiming);
        cudaEventCreateWithFlags(&g_evKV,   cudaEventDisableTiming);
    }
};
static _StreamInit _stream_init;

// ---------------- helpers ----------------------------------------------------
__device__ __forceinline__ float gelu_tanh(float x) {
    float x3 = x*x*x;
    return 0.5f*x*(1.f + tanhf(0.7978845608028654f*(x + 0.044715f*x3)));
}
__device__ __forceinline__ uint32_t f2h2(float lo, float hi) {
    __half2 h = __floats2half2_rn(lo, hi);
    return *reinterpret_cast<uint32_t*>(&h);
}
__device__ __forceinline__ void mma_f16(float* d, const uint32_t* a, const uint32_t* b) {
    asm volatile(
        "mma.sync.aligned.m16n8k16.row.col.f32.f16.f16.f32 "
        "{%0,%1,%2,%3}, {%4,%5,%6,%7}, {%8,%9}, {%0,%1,%2,%3};\n"
        : "+f"(d[0]), "+f"(d[1]), "+f"(d[2]), "+f"(d[3])
        : "r"(a[0]), "r"(a[1]), "r"(a[2]), "r"(a[3]), "r"(b[0]), "r"(b[1]));
}
__device__ __forceinline__ void ldsm4(uint32_t* r, uint32_t addr) {
    asm volatile("ldmatrix.sync.aligned.m8n8.x4.shared.b16 {%0,%1,%2,%3}, [%4];"
        : "=r"(r[0]), "=r"(r[1]), "=r"(r[2]), "=r"(r[3]) : "r"(addr));
}
__device__ __forceinline__ void ldsm4t(uint32_t* r, uint32_t addr) {
    asm volatile("ldmatrix.sync.aligned.m8n8.x4.trans.shared.b16 {%0,%1,%2,%3}, [%4];"
        : "=r"(r[0]), "=r"(r[1]), "=r"(r[2]), "=r"(r[3]) : "r"(addr));
}
__device__ __forceinline__ void cpa16(uint32_t dst, const void* src) {
    asm volatile("cp.async.ca.shared.global [%0], [%1], 16;\n" :: "r"(dst), "l"(src));
}
__device__ __forceinline__ void cpa_commit() { asm volatile("cp.async.commit_group;\n"); }
__device__ __forceinline__ void cpa_wait1()  { asm volatile("cp.async.wait_group 1;\n"); }
__device__ __forceinline__ void cpa_wait0()  { asm volatile("cp.async.wait_group 0;\n"); }

// ---------------- small utility kernels --------------------------------------
__global__ void f2h8_k(const float* __restrict__ p0, const float* __restrict__ p1,
                       const float* __restrict__ p2, const float* __restrict__ p3,
                       const float* __restrict__ p4, const float* __restrict__ p5,
                       const float* __restrict__ p6, const float* __restrict__ p7,
                       __half* __restrict__ out) {
    const float* src;
    switch (blockIdx.y) {
        case 0: src = p0; break; case 1: src = p1; break;
        case 2: src = p2; break; case 3: src = p3; break;
        case 4: src = p4; break; case 5: src = p5; break;
        case 6: src = p6; break; default: src = p7; break;
    }
    int i = (blockIdx.x*256 + threadIdx.x)*8;
    float4 a = *(const float4*)&src[i];
    float4 b = *(const float4*)&src[i+4];
    *(uint4*)&out[(size_t)blockIdx.y*(C_*C_) + i] =
        make_uint4(f2h2(a.x,a.y), f2h2(a.z,a.w), f2h2(b.x,b.y), f2h2(b.z,b.w));
}
__global__ void f2hm_k(const float* __restrict__ w1, const float* __restrict__ w2,
                       const float* __restrict__ audio,
                       __half* __restrict__ wh, __half* __restrict__ ah) {
    const float* src; __half* dst;
    switch (blockIdx.y) {
        case 0: src = w1; dst = wh + WOFF_W1; break;
        case 1: src = w2; dst = wh + WOFF_W2; break;
        case 2: src = audio; dst = ah; break;
        default: src = audio + 4*1024*1024; dst = ah + 4*1024*1024; break;
    }
    int i = (blockIdx.x*256 + threadIdx.x)*8;
    float4 a = *(const float4*)&src[i];
    float4 b = *(const float4*)&src[i+4];
    *(uint4*)&dst[i] = make_uint4(f2h2(a.x,a.y), f2h2(a.z,a.w),
                                  f2h2(b.x,b.y), f2h2(b.z,b.w));
}

// ---------------- adaLN modulation: split-K (32), deterministic 2-stage ------
__global__ void mod1_k(const float* __restrict__ c, const float* __restrict__ w,
                       float* __restrict__ part) {
    __shared__ float sc[B_][32];
    int tid = threadIdx.x;
    int s   = blockIdx.y;
    int k0  = s*32;
    if (tid < B_*32) {
        int b = tid >> 5, k = tid & 31;
        float v = c[b*C_ + k0 + k];
        sc[b][k] = v / (1.f + __expf(-v));
    }
    __syncthreads();
    int col = blockIdx.x*256 + tid;
    float acc[B_];
    #pragma unroll
    for (int b = 0; b < B_; b++) acc[b] = 0.f;
    #pragma unroll 8
    for (int k = 0; k < 32; k++) {
        float wv = w[(size_t)(k0 + k)*SIXC + col];
        #pragma unroll
        for (int b = 0; b < B_; b++) acc[b] += sc[b][k]*wv;
    }
    float* dst = part + (size_t)s*B_*SIXC;
    #pragma unroll
    for (int b = 0; b < B_; b++) dst[b*SIXC + col] = acc[b];
}
__global__ void mod2_k(const float* __restrict__ part, const float* __restrict__ bias,
                       float* __restrict__ mod) {
    int col = blockIdx.x*256 + threadIdx.x;
    float bb = bias[col];
    #pragma unroll
    for (int b = 0; b < B_; b++) {
        float s = 0.f;
        #pragma unroll
        for (int p = 0; p < NSPLIT; p++)
            s += part[(size_t)p*B_*SIXC + b*SIXC + col];
        mod[b*SIXC + col] = s + bb;
    }
}

// ---------------- LN (no affine) + modulate -> fp16 --------------------------
template<int COPY>
__global__ void ln_mod_k(const float* __restrict__ x, const float* __restrict__ mod,
                         int shiftOff, int scaleOff, __half* __restrict__ out,
                         float* __restrict__ res) {
    int row = blockIdx.x;
    int b   = row & (B_-1);
    int tid = threadIdx.x;
    const float* xr = x + (size_t)row*C_;
    float4 v = *(const float4*)&xr[tid*4];
    if (COPY) *(float4*)&res[(size_t)row*C_ + tid*4] = v;
    float s  = v.x + v.y + v.z + v.w;
    float s2 = v.x*v.x + v.y*v.y + v.z*v.z + v.w*v.w;
    #pragma unroll
    for (int o = 16; o; o >>= 1) {
        s  += __shfl_xor_sync(0xffffffffu, s,  o);
        s2 += __shfl_xor_sync(0xffffffffu, s2, o);
    }
    __shared__ float red[2][8];
    int w = tid >> 5, ln = tid & 31;
    if (ln == 0) { red[0][w] = s; red[1][w] = s2; }
    __syncthreads();
    s = 0.f; s2 = 0.f;
    #pragma unroll
    for (int i = 0; i < 8; i++) { s += red[0][i]; s2 += red[1][i]; }
    float mu   = s * (1.f/C_);
    float var  = s2 * (1.f/C_) - mu*mu;
    float rstd = rsqrtf(var + 1e-6f);
    const float* sh = mod + b*SIXC + shiftOff + tid*4;
    const float* sc = mod + b*SIXC + scaleOff + tid*4;
    float4 shv = *(const float4*)sh;
    float4 scv = *(const float4*)sc;
    float m0 = (v.x-mu)*rstd*(1.f+scv.x) + shv.x;
    float m1 = (v.y-mu)*rstd*(1.f+scv.y) + shv.y;
    float m2 = (v.z-mu)*rstd*(1.f+scv.z) + shv.z;
    float m3 = (v.w-mu)*rstd*(1.f+scv.w) + shv.w;
    *(uint2*)&out[(size_t)row*C_ + tid*4] = make_uint2(f2h2(m0,m1), f2h2(m2,m3));
}

// ---------------- fp16 GEMM 128x128, BK=32, 128 thr, warp tile 64x64 ---------
// Mainloop: all 16 ldmatrix (both k-slices) issued before the 64 MMAs.
#define SAW 12
#define SBW 68
#define ABUF (2*128*SAW)
#define BBUF (2*16*SBW)

template<int EPI, typename OT>
__device__ __forceinline__ void gemm_body(
    uint32_t* AsS, uint32_t* BsS,
    const __half* __restrict__ A, const __half* __restrict__ W,
    const float* __restrict__ bias, OT* __restrict__ out,
    const float* __restrict__ gate,
    int K, int N, int row0, int col0, size_t ostride, int ocol0)
{
    int tid  = threadIdx.x;
    int lane = tid & 31, wid = tid >> 5;
    int g    = lane >> 2, tig = lane & 3;
    int wm   = wid >> 1, wn = wid & 1;

    uint32_t sA0 = (uint32_t)__cvta_generic_to_shared(AsS);
    uint32_t sB0 = (uint32_t)__cvta_generic_to_shared(BsS);

    float acc[4][8][4];
    #pragma unroll
    for (int i = 0; i < 4; i++)
        #pragma unroll
        for (int j = 0; j < 8; j++)
            #pragma unroll
            for (int q = 0; q < 4; q++) acc[i][j][q] = 0.f;

    auto load_chunk = [&](int k0, int bf) {
        #pragma unroll
        for (int p = 0; p < 4; p++) {
            int idx = tid + p*128;
            int row = idx >> 2, q = idx & 3, ks = q >> 1, hs = q & 1;
            const __half* src = A + (size_t)(row0 + row)*K + k0 + ks*16 + hs*8;
            uint32_t dst = sA0 + (bf*ABUF + ks*128*SAW + row*SAW + hs*4)*4;
            cpa16(dst, src);
        }
        #pragma unroll
        for (int p = 0; p < 4; p++) {
            int idx = tid + p*128;
            int kr = idx >> 4, nc = idx & 15;
            const __half* src = W + (size_t)(k0 + kr)*N + col0 + nc*8;
            uint32_t dst = sB0 + (bf*BBUF + (kr>>4)*16*SBW + (kr&15)*SBW + nc*4)*4;
            cpa16(dst, src);
        }
        cpa_commit();
    };

    load_chunk(0, 0);

    int buf = 0;
    int nchunk = K >> 5;
    uint32_t aoff = ((wm*64 + (lane & 15))*SAW + ((lane >> 4) << 2))*4;
    uint32_t boff = ((lane & 15)*SBW + wn*32 + ((lane >> 4) << 2))*4;
    for (int ch = 0; ch < nchunk; ch++) {
        bool more = (ch + 1 < nchunk);
        if (more) { load_chunk((ch + 1)*32, buf ^ 1); cpa_wait1(); }
        else      { cpa_wait0(); }
        __syncthreads();

        uint32_t sAb = sA0 + (buf*ABUF)*4;
        uint32_t sBb = sB0 + (buf*BBUF)*4;

        // issue ALL fragment loads (both k-slices) first
        uint32_t af0[4][4], af1[4][4], bq0[4][4], bq1[4][4];
        #pragma unroll
        for (int mt = 0; mt < 4; mt++) {
            ldsm4(af0[mt], sAb + aoff + (mt*16*SAW)*4);
            ldsm4(af1[mt], sAb + aoff + (128*SAW + mt*16*SAW)*4);
        }
        #pragma unroll
        for (int hf = 0; hf < 4; hf++) {
            ldsm4t(bq0[hf], sBb + boff + (hf*8)*4);
            ldsm4t(bq1[hf], sBb + boff + (16*SBW + hf*8)*4);
        }
        // then the 64 MMAs back-to-back
        #pragma unroll
        for (int mt = 0; mt < 4; mt++)
            #pragma unroll
            for (int nt = 0; nt < 8; nt++)
                mma_f16(acc[mt][nt], af0[mt], &bq0[nt >> 1][(nt & 1)*2]);
        #pragma unroll
        for (int mt = 0; mt < 4; mt++)
            #pragma unroll
            for (int nt = 0; nt < 8; nt++)
                mma_f16(acc[mt][nt], af1[mt], &bq1[nt >> 1][(nt & 1)*2]);

        __syncthreads();
        buf ^= 1;
    }

    #pragma unroll
    for (int mt = 0; mt < 4; mt++) {
        int rbase = row0 + wm*64 + mt*16 + g;
        #pragma unroll
        for (int half = 0; half < 2; half++) {
            int rr = rbase + 8*half;
            int bb = rr & (B_-1);
            OT* orow = out + (size_t)rr*ostride + ocol0;
            #pragma unroll
            for (int nt = 0; nt < 8; nt++) {
                int cl = col0 + wn*64 + nt*8 + 2*tig;
                float v0 = acc[mt][nt][2*half + 0] + bias[cl];
                float v1 = acc[mt][nt][2*half + 1] + bias[cl+1];
                if (EPI == 2) {
                    float* fr = (float*)orow;
                    fr[cl]   += gate[bb*SIXC + cl  ]*v0;
                    fr[cl+1] += gate[bb*SIXC + cl+1]*v1;
                } else if (EPI == 1) {
                    *(uint32_t*)&orow[cl] = f2h2(gelu_tanh(v0), gelu_tanh(v1));
                } else {
                    *(uint32_t*)&orow[cl] = f2h2(v0, v1);
                }
            }
        }
    }
}

template<int EPI, typename OT>
__global__ void __launch_bounds__(128, 2)
hgemm_k(const __half* __restrict__ A, const __half* __restrict__ W,
        const float* __restrict__ bias, OT* __restrict__ out,
        const float* __restrict__ gate, int K, int N) {
    __shared__ __align__(16) uint32_t As[2*ABUF];
    __shared__ __align__(16) uint32_t Bs[2*BBUF];
    gemm_body<EPI, OT>(As, Bs, A, W, bias, out, gate, K, N,
                       blockIdx.y*128, blockIdx.x*128, N, 0);
}

__global__ void __launch_bounds__(128, 2)
hgemm_qkv_k(const __half* __restrict__ A, const __half* __restrict__ Wbase,
            const float* __restrict__ b0, const float* __restrict__ b1,
            const float* __restrict__ b2,
            __half* __restrict__ out, int woff0, int K) {
    __shared__ __align__(16) uint32_t As[2*ABUF];
    __shared__ __align__(16) uint32_t Bs[2*BBUF];
    int sel = blockIdx.x >> 3;
    int nb  = blockIdx.x & 7;
    const __half* W    = Wbase + woff0 + sel*(C_*C_);
    const float* bias  = (sel == 0) ? b0 : (sel == 1) ? b1 : b2;
    gemm_body<0, __half>(As, Bs, A, W, bias, out, nullptr, K, C_,
                         blockIdx.y*128, nb*128, 3*C_, sel*C_);
}
__global__ void __launch_bounds__(128, 2)
hgemm_kv_k(const __half* __restrict__ A, const __half* __restrict__ Wbase,
           const float* __restrict__ b1, const float* __restrict__ b2,
           __half* __restrict__ out, int woff0, int K) {
    __shared__ __align__(16) uint32_t As[2*ABUF];
    __shared__ __align__(16) uint32_t Bs[2*BBUF];
    int sel = 1 + (blockIdx.x >> 3);
    int nb  = blockIdx.x & 7;
    const __half* W    = Wbase + woff0 + sel*(C_*C_);
    const float* bias  = (sel == 1) ? b1 : b2;
    gemm_body<0, __half>(As, Bs, A, W, bias, out, nullptr, K, C_,
                         blockIdx.y*128, nb*128, 3*C_, sel*C_);
}
__global__ void __launch_bounds__(128, 2)
hgemm_q_k(const __half* __restrict__ A, const __half* __restrict__ Wbase,
          const float* __restrict__ b0, __half* __restrict__ out,
          int woff0, int K) {
    __shared__ __align__(16) uint32_t As[2*ABUF];
    __shared__ __align__(16) uint32_t Bs[2*BBUF];
    gemm_body<0, __half>(As, Bs, A, Wbase + woff0, b0, out, nullptr, K, C_,
                         blockIdx.y*128, blockIdx.x*128, 3*C_, 0);
}

// ---------------- register-resident fp16 flash attention ---------------------
#define KVW 36
#define ATT_SMEM ((128*KVW + 4*64*KVW)*4 + 1024*4)
__global__ void __launch_bounds__(256, 2)
fattn_k(const __half* __restrict__ QKV, const int* __restrict__ mask,
        __half* __restrict__ Y, int Tk) {
    extern __shared__ uint32_t smu[];
    uint32_t* Qs = smu;
    uint32_t* Ks = Qs + 128*KVW;
    uint32_t* Vs = Ks + 2*64*KVW;
    int*      Msk = (int*)(Vs + 2*64*KVW);

    int tid  = threadIdx.x;
    int lane = tid & 31, wid = tid >> 5;
    int g    = lane >> 2, tig = lane & 3;
    int qbase = wid*16;
    int q0 = blockIdx.x*128, h = blockIdx.y, b = blockIdx.z;
    size_t hoff = (size_t)h*D_;
    const int RS = 3*C_;
    const __half* Kp = QKV + C_;
    const __half* Vp = QKV + 2*C_;

    uint32_t sQ = (uint32_t)__cvta_generic_to_shared(Qs);
    uint32_t sK = (uint32_t)__cvta_generic_to_shared(Ks);
    uint32_t sV = (uint32_t)__cvta_generic_to_shared(Vs);

    for (int i = tid; i < (Tk >> 2); i += 256)
        *(int4*)&Msk[i*4] = *(const int4*)&mask[(size_t)b*Tk + i*4];

    #pragma unroll
    for (int p = 0; p < 4; p++) {
        int idx = tid + p*256;
        int r = idx >> 3, c8 = idx & 7;
        *(uint4*)&Qs[r*KVW + c8*4] =
            *(const uint4*)&QKV[((size_t)(q0+r)*B_ + b)*RS + hoff + c8*8];
    }

    auto load_kv = [&](int k0, int bf) {
        #pragma unroll
        for (int p = 0; p < 2; p++) {
            int idx = tid + p*256;
            int r = idx >> 3, c8 = idx & 7;
            size_t gi = ((size_t)(k0+r)*B_ + b)*RS + hoff + c8*8;
            uint32_t off = (bf*64*KVW + r*KVW + c8*4)*4;
            cpa16(sK + off, Kp + gi);
            cpa16(sV + off, Vp + gi);
        }
        cpa_commit();
    };
    load_kv(0, 0);

    float m0 = -1e30f, m1 = -1e30f, l0 = 0.f, l1 = 0.f;
    float oacc[8][4];
    #pragma unroll
    for (int i = 0; i < 8; i++)
        #pragma unroll
        for (int j = 0; j < 4; j++) oacc[i][j] = 0.f;

    uint32_t qaddr = sQ + ((qbase + (lane & 15))*KVW + ((lane >> 4) << 2))*4;
    uint32_t vfix  = ((lane & 15)*KVW + ((lane >> 4) << 2))*4;

    int ntile = Tk >> 6;
    for (int kt = 0; kt < ntile; kt++) {
        int buf = kt & 1;
        cpa_wait0();
        __syncthreads();
        if (kt + 1 < ntile) load_kv((kt + 1)*64, buf ^ 1);

        const uint32_t* Ksb = Ks + buf*64*KVW;
        float sacc[8][4];
        #pragma unroll
        for (int i = 0; i < 8; i++)
            #pragma unroll
            for (int j = 0; j < 4; j++) sacc[i][j] = 0.f;
        #pragma unroll
        for (int ks = 0; ks < 4; ks++) {
            uint32_t qf[4];
            ldsm4(qf, qaddr + ks*32);
            #pragma unroll
            for (int nt = 0; nt < 8; nt++) {
                uint32_t bf[2];
                const uint32_t* kp = &Ksb[(nt*8 + g)*KVW + ks*8 + tig];
                bf[0] = kp[0]; bf[1] = kp[4];
                mma_f16(sacc[nt], qf, bf);
            }
        }

        float mx0 = -1e30f, mx1 = -1e30f;
        #pragma unroll
        for (int nt = 0; nt < 8; nt++) {
            int2 mm = *(const int2*)&Msk[kt*64 + nt*8 + 2*tig];
            sacc[nt][0] = mm.x ? -1e30f : sacc[nt][0]*0.125f;
            sacc[nt][1] = mm.y ? -1e30f : sacc[nt][1]*0.125f;
            sacc[nt][2] = mm.x ? -1e30f : sacc[nt][2]*0.125f;
            sacc[nt][3] = mm.y ? -1e30f : sacc[nt][3]*0.125f;
            mx0 = fmaxf(mx0, fmaxf(sacc[nt][0], sacc[nt][1]));
            mx1 = fmaxf(mx1, fmaxf(sacc[nt][2], sacc[nt][3]));
        }
        mx0 = fmaxf(mx0, __shfl_xor_sync(0xffffffffu, mx0, 1));
        mx0 = fmaxf(mx0, __shfl_xor_sync(0xffffffffu, mx0, 2));
        mx1 = fmaxf(mx1, __shfl_xor_sync(0xffffffffu, mx1, 1));
        mx1 = fmaxf(mx1, __shfl_xor_sync(0xffffffffu, mx1, 2));
        float mn0 = fmaxf(m0, mx0), mn1 = fmaxf(m1, mx1);
        float scl0 = __expf(m0 - mn0), scl1 = __expf(m1 - mn1);
        m0 = mn0; m1 = mn1;

        uint32_t pf[4][4];
        float rs0 = 0.f, rs1 = 0.f;
        #pragma unroll
        for (int nt = 0; nt < 8; nt++) {
            float p0 = (sacc[nt][0] > -1e29f) ? __expf(sacc[nt][0] - mn0) : 0.f;
            float p1 = (sacc[nt][1] > -1e29f) ? __expf(sacc[nt][1] - mn0) : 0.f;
            float p2 = (sacc[nt][2] > -1e29f) ? __expf(sacc[nt][2] - mn1) : 0.f;
            float p3 = (sacc[nt][3] > -1e29f) ? __expf(sacc[nt][3] - mn1) : 0.f;
            rs0 += p0 + p1; rs1 += p2 + p3;
            pf[nt >> 1][0 + 2*(nt & 1)] = f2h2(p0, p1);
            pf[nt >> 1][1 + 2*(nt & 1)] = f2h2(p2, p3);
        }
        rs0 += __shfl_xor_sync(0xffffffffu, rs0, 1);
        rs0 += __shfl_xor_sync(0xffffffffu, rs0, 2);
        rs1 += __shfl_xor_sync(0xffffffffu, rs1, 1);
        rs1 += __shfl_xor_sync(0xffffffffu, rs1, 2);
        l0 = l0*scl0 + rs0;
        l1 = l1*scl1 + rs1;

        #pragma unroll
        for (int dt = 0; dt < 8; dt++) {
            oacc[dt][0] *= scl0; oacc[dt][1] *= scl0;
            oacc[dt][2] *= scl1; oacc[dt][3] *= scl1;
        }
        uint32_t vb = sV + (buf*64*KVW)*4;
        #pragma unroll
        for (int ks = 0; ks < 4; ks++) {
            uint32_t bv[4][4];
            #pragma unroll
            for (int j = 0; j < 4; j++)
                ldsm4t(bv[j], vb + (ks*16*KVW + j*8)*4 + vfix);
            #pragma unroll
            for (int dt = 0; dt < 8; dt++)
                mma_f16(oacc[dt], pf[ks], &bv[dt >> 1][(dt & 1)*2]);
        }
    }

    float inv0 = 1.f / l0, inv1 = 1.f / l1;
    int r0 = q0 + qbase + g;
    #pragma unroll
    for (int dt = 0; dt < 8; dt++) {
        int dd = dt*8 + 2*tig;
        *(uint32_t*)&Y[((size_t) r0     *B_ + b)*C_ + hoff + dd] =
            f2h2(oacc[dt][0]*inv0, oacc[dt][1]*inv0);
        *(uint32_t*)&Y[((size_t)(r0 + 8)*B_ + b)*C_ + hoff + dd] =
            f2h2(oacc[dt][2]*inv1, oacc[dt][3]*inv1);
    }
}

// ---------------- launch -----------------------------------------------------
extern "C" void kernel_launch(void* const* d_in, const int* in_sizes, int n_in,
                              void* d_out, int out_size) {
    const float* x     = (const float*)d_in[0];
    const float* c     = (const float*)d_in[1];
    const int*   pmask = (const int*)  d_in[2];
    const float* audio = (const float*)d_in[3];
    const int*   amask = (const int*)  d_in[4];
    const float* w_ada = (const float*)d_in[5];
    const float* b_ada = (const float*)d_in[6];
    const float* wq = (const float*)d_in[7];   const float* bq = (const float*)d_in[8];
    const float* wk = (const float*)d_in[9];   const float* bk = (const float*)d_in[10];
    const float* wv = (const float*)d_in[11];  const float* bv = (const float*)d_in[12];
    const float* wo = (const float*)d_in[13];  const float* bo = (const float*)d_in[14];
    const float* cwq = (const float*)d_in[15]; const float* cbq = (const float*)d_in[16];
    const float* cwk = (const float*)d_in[17]; const float* cbk = (const float*)d_in[18];
    const float* cwv = (const float*)d_in[19]; const float* cbv = (const float*)d_in[20];
    const float* cwo = (const float*)d_in[21]; const float* cbo = (const float*)d_in[22];
    const float* w1 = (const float*)d_in[23];  const float* b1 = (const float*)d_in[24];
    const float* w2 = (const float*)d_in[25];  const float* b2 = (const float*)d_in[26];
    float* out = (float*)d_out;

    float  *modp, *partp;
    __half *whp, *ahp, *lnp, *qkvp, *qkv2p, *yp, *hp;
    cudaGetSymbolAddress((void**)&modp,  g_mod);
    cudaGetSymbolAddress((void**)&partp, g_modpart);
    cudaGetSymbolAddress((void**)&whp,   g_wh);
    cudaGetSymbolAddress((void**)&ahp,   g_ah);
    cudaGetSymbolAddress((void**)&lnp,   g_lnh);
    cudaGetSymbolAddress((void**)&qkvp,  g_qkv);
    cudaGetSymbolAddress((void**)&qkv2p, g_qkv2);
    cudaGetSymbolAddress((void**)&yp,    g_yh);
    cudaGetSymbolAddress((void**)&hp,    g_hh);

    cudaFuncSetAttribute(fattn_k, cudaFuncAttributeMaxDynamicSharedMemorySize, ATT_SMEM);

    dim3 gQKV(24, 64);
    dim3 gKV(16, 64);
    dim3 gQ(8, 64);
    dim3 gC(8, 64);
    dim3 gM(32, 64);
    dim3 gA(T_/128, H_, B_);

    // ---- fork side stream: weight/audio converts + cross K/V projection ----
    cudaEventRecord(g_evFork, 0);
    cudaStreamWaitEvent(g_s1, g_evFork, 0);
    f2h8_k<<<dim3((C_*C_)/2048, 8), 256, 0, g_s1>>>(wq, wk, wv, wo, cwq, cwk, cwv, cwo, whp);
    f2hm_k<<<dim3(2048, 4), 256, 0, g_s1>>>(w1, w2, audio, whp, ahp);
    cudaEventRecord(g_evConv, g_s1);
    hgemm_kv_k<<<gKV, 128, 0, g_s1>>>(ahp, whp, cbk, cbv, qkv2p, WOFF_CQ, C_);
    cudaEventRecord(g_evKV, g_s1);

    // ---- main stream prologue (parallel with converts) ----
    mod1_k<<<dim3(SIXC/256, NSPLIT), 256>>>(c, w_ada, partp);
    mod2_k<<<SIXC/256, 256>>>(partp, b_ada, modp);
    ln_mod_k<1><<<R_, 256>>>(x, modp, 0, C_, lnp, out);

    // ---- self attention ----
    cudaStreamWaitEvent(0, g_evConv, 0);
    hgemm_qkv_k<<<gQKV, 128>>>(lnp, whp, bq, bk, bv, qkvp, WOFF_Q, C_);
    fattn_k<<<gA, 256, ATT_SMEM>>>(qkvp, pmask, yp, T_);
    hgemm_k<2, float><<<gC, 128>>>(yp, whp + WOFF_O, bo, out, modp + 2*C_, C_, C_);

    // ---- cross attention ----
    ln_mod_k<0><<<R_, 256>>>(out, modp, 0, C_, lnp, nullptr);
    hgemm_q_k<<<gQ, 128>>>(lnp, whp, cbq, qkv2p, WOFF_CQ, C_);
    cudaStreamWaitEvent(0, g_evKV, 0);
    fattn_k<<<gA, 256, ATT_SMEM>>>(qkv2p, amask, yp, TA_);
    hgemm_k<2, float><<<gC, 128>>>(yp, whp + WOFF_CO, cbo, out, modp + 2*C_, C_, C_);

    // ---- MLP ----
    ln_mod_k<0><<<R_, 256>>>(out, modp, 3*C_, 4*C_, lnp, nullptr);
    hgemm_k<1, __half><<<gM, 128>>>(lnp, whp + WOFF_W1, b1, hp, nullptr, C_, M_);
    hgemm_k<2, float><<<gC, 128>>>(hp, whp + WOFF_W2, b2, out, modp + 5*C_, M_, C_);
}